// round 15
// baseline (speedup 1.0000x reference)
#include <cuda_runtime.h>
#include <cuda_bf16.h>
#include <cstdint>

// ---------------------------------------------------------------------------
// Problem constants: B=64, T=4, N=6, IMG=128, CIN=3, VE=64, D=256, P=4, R=8
// ---------------------------------------------------------------------------
#define NB 64
#define NT 4
#define NN 6
#define NBT 256            // B*T
#define NROI 1536          // B*T*N
#define NROW 384           // B*N
#define ND 256
#define SD (NROW*ND)
#define NROLL 8

// ---------------------------------------------------------------------------
// Device scratch
// ---------------------------------------------------------------------------
__device__ __nv_bfloat16 g_x4h[(size_t)NBT * 128 * 128 * 4];
__device__ __nv_bfloat16 g_x4l[(size_t)NBT * 128 * 128 * 4];
__device__ __nv_bfloat16 g_w1h[9 * 64 * 4];
__device__ __nv_bfloat16 g_w1l[9 * 64 * 4];
__device__ __nv_bfloat16 g_f1h[(size_t)NBT * 64 * 64 * 64];   // channel-last
__device__ __nv_bfloat16 g_f1l[(size_t)NBT * 64 * 64 * 64];
__device__ __nv_bfloat16 g_w2h[9 * 64 * 64];
__device__ __nv_bfloat16 g_w2l[9 * 64 * 64];
__device__ float g_f2[(size_t)NBT * 64 * 32 * 32];
__device__ float g_pool [NROI * 1024];
__device__ float g_obj  [NROI * ND];
__device__ float g_emb1 [NROI * ND];
__device__ float g_emb2 [NROI * ND];
__device__ float g_sttmp[NROI * ND];
__device__ float g_selfd[4 * SD];
__device__ float g_u[4 * SD];
__device__ float g_v[4 * SD];
__device__ float g_aggp[4 * SD];
__device__ float g_r[NROW];
__device__ __nv_bfloat16 g_Oh[4 * SD],  g_Ol[4 * SD];
__device__ __nv_bfloat16 g_Ph[8 * SD],  g_Pl[8 * SD];
__device__ __nv_bfloat16 g_th[4 * SD],  g_tl[4 * SD];
__device__ __nv_bfloat16 g_ah[4 * SD],  g_al[4 * SD];
__device__ __nv_bfloat16 g_csh[NROW * 1024], g_csl[NROW * 1024];
#define OFF_SELF 0
#define OFF_REL  262144
#define OFF_AFF  786432
#define OFF_OUT  1048576
#define OFF_AGG  1572864
#define WTOTAL   1835008
__device__ __nv_bfloat16 g_wh[WTOTAL];
__device__ __nv_bfloat16 g_wl[WTOTAL];

// ---------------------------------------------------------------------------
// conversions
// ---------------------------------------------------------------------------
__global__ void cvt2_kernel(const float* __restrict__ w2) {
    int i = blockIdx.x * 256 + threadIdx.x;
    if (i >= 9 * 64 * 64) return;
    int ci = i & 63, n = (i >> 6) & 63, tap = i >> 12;
    float v = w2[(size_t)n * 576 + ci * 9 + tap];
    __nv_bfloat16 h = __float2bfloat16(v);
    g_w2h[i] = h;
    g_w2l[i] = __float2bfloat16(v - __bfloat162float(h));
}

__global__ void cvt1_kernel(const float* __restrict__ w1) {
    int i = blockIdx.x * 256 + threadIdx.x;
    if (i >= 576) return;
    int co = i % 64, tap = i / 64;
    __nv_bfloat16 hv[4], lv[4];
#pragma unroll
    for (int ci = 0; ci < 3; ++ci) {
        float v = w1[(size_t)co * 27 + ci * 9 + tap];
        hv[ci] = __float2bfloat16(v);
        lv[ci] = __float2bfloat16(v - __bfloat162float(hv[ci]));
    }
    hv[3] = __float2bfloat16(0.f);
    lv[3] = __float2bfloat16(0.f);
    *(uint2*)&g_w1h[(size_t)i * 4] = *(uint2*)hv;
    *(uint2*)&g_w1l[(size_t)i * 4] = *(uint2*)lv;
}

__global__ void xcvt_kernel(const float* __restrict__ x) {
    size_t p = (size_t)blockIdx.x * 256 + threadIdx.x;
    size_t bt = p >> 14, px = p & 16383;
    const float* xp = x + bt * 3 * 16384 + px;
    __nv_bfloat16 hv[4], lv[4];
#pragma unroll
    for (int ci = 0; ci < 3; ++ci) {
        float v = xp[(size_t)ci * 16384];
        hv[ci] = __float2bfloat16(v);
        lv[ci] = __float2bfloat16(v - __bfloat162float(hv[ci]));
    }
    hv[3] = __float2bfloat16(0.f);
    lv[3] = __float2bfloat16(0.f);
    *(uint2*)&g_x4h[p * 4] = *(uint2*)hv;
    *(uint2*)&g_x4l[p * 4] = *(uint2*)lv;
}

// vectorized: 4 elements per thread
struct CvtArgs { const float* src[5]; int size[5]; int off[5]; };
__global__ void cvt_kernel(CvtArgs c) {
    int seg = blockIdx.y;
    int i4 = (blockIdx.x * 256 + threadIdx.x) * 4;
    if (i4 >= c.size[seg]) return;
    float4 v = *(const float4*)(c.src[seg] + i4);
    __nv_bfloat16 hv[4], lv[4];
    hv[0] = __float2bfloat16(v.x); lv[0] = __float2bfloat16(v.x - __bfloat162float(hv[0]));
    hv[1] = __float2bfloat16(v.y); lv[1] = __float2bfloat16(v.y - __bfloat162float(hv[1]));
    hv[2] = __float2bfloat16(v.z); lv[2] = __float2bfloat16(v.z - __bfloat162float(hv[2]));
    hv[3] = __float2bfloat16(v.w); lv[3] = __float2bfloat16(v.w - __bfloat162float(hv[3]));
    *(uint2*)&g_wh[c.off[seg] + i4] = *(uint2*)hv;
    *(uint2*)&g_wl[c.off[seg] + i4] = *(uint2*)lv;
}

// ---------------------------------------------------------------------------
__global__ void r_kernel(const float* __restrict__ rois) {
    int i = blockIdx.x * 128 + threadIdx.x;
    if (i >= NROW) return;
    int b = i / NN, n = i % NN;
    float s = 0.f;
    for (int t = 0; t < NT; ++t) {
        const float* ro = rois + (size_t)(((b * NT + t) * NN) + n) * 5;
        s += ((ro[4] - ro[2]) * 0.5f + (ro[3] - ro[1]) * 0.5f) * 0.5f;
    }
    g_r[i] = s * 0.25f;
}

// ---------------------------------------------------------------------------
#define MMA_BF16(d, a0, a1, a2, a3, b0, b1)                                    \
    asm volatile(                                                              \
        "mma.sync.aligned.m16n8k16.row.col.f32.bf16.bf16.f32 "                \
        "{%0,%1,%2,%3},{%4,%5,%6,%7},{%8,%9},{%0,%1,%2,%3};"                  \
        : "+f"(d[0]), "+f"(d[1]), "+f"(d[2]), "+f"(d[3])                       \
        : "r"(a0), "r"(a1), "r"(a2), "r"(a3), "r"(b0), "r"(b1))

// ---------------------------------------------------------------------------
// conv1 via tensor cores (proven round 11)
// ---------------------------------------------------------------------------
__global__ void conv1_mma_kernel(const float* __restrict__ b1) {
    __shared__ __nv_bfloat16 Ah[128 * 56];
    __shared__ __nv_bfloat16 Al[128 * 56];
    __shared__ __nv_bfloat16 Bh[64 * 56];
    __shared__ __nv_bfloat16 Bl[64 * 56];

    int tid = threadIdx.x;
    int w = tid >> 5, lane = tid & 31;
    int g = lane >> 2, tq = lane & 3;
    int bx = blockIdx.x, bt = blockIdx.y;
    int oy0 = bx * 2;
    const __nv_bfloat16* xh = g_x4h + (size_t)bt * 16384 * 4;
    const __nv_bfloat16* xl = g_x4l + (size_t)bt * 16384 * 4;

    {
        uint4 z = make_uint4(0u, 0u, 0u, 0u);
        uint4* a4h = (uint4*)Ah; uint4* a4l = (uint4*)Al;
        for (int i = tid; i < 896; i += 256) { a4h[i] = z; a4l[i] = z; }
        uint4* b4h = (uint4*)Bh; uint4* b4l = (uint4*)Bl;
        for (int i = tid; i < 448; i += 256) { b4h[i] = z; b4l[i] = z; }
    }
    __syncthreads();

    for (int idx = tid; idx < 1152; idx += 256) {
        int t9 = idx >> 7, m = idx & 127;
        int kh = t9 / 3, kw = t9 - 3 * kh;
        int dy = m >> 6, ox = m & 63;
        int iy = 2 * (oy0 + dy) + kh;
        int ix = 2 * ox + kw;
        if (iy < 128 && ix < 128) {
            size_t src = ((size_t)iy * 128 + ix) * 4;
            *(uint2*)&Ah[m * 56 + t9 * 4] = *(const uint2*)&xh[src];
            *(uint2*)&Al[m * 56 + t9 * 4] = *(const uint2*)&xl[src];
        }
    }
    for (int idx = tid; idx < 576; idx += 256) {
        int t9 = idx / 64, co = idx % 64;
        *(uint2*)&Bh[co * 56 + t9 * 4] = *(const uint2*)&g_w1h[(size_t)idx * 4];
        *(uint2*)&Bl[co * 56 + t9 * 4] = *(const uint2*)&g_w1l[(size_t)idx * 4];
    }
    __syncthreads();

    float d[8][4] = {};
#pragma unroll
    for (int ks = 0; ks < 3; ++ks) {
        int k0 = ks * 16 + tq * 2;
        int r0 = w * 16 + g;
        uint32_t ah0 = *(const uint32_t*)&Ah[r0 * 56 + k0];
        uint32_t ah1 = *(const uint32_t*)&Ah[(r0 + 8) * 56 + k0];
        uint32_t ah2 = *(const uint32_t*)&Ah[r0 * 56 + k0 + 8];
        uint32_t ah3 = *(const uint32_t*)&Ah[(r0 + 8) * 56 + k0 + 8];
        uint32_t al0 = *(const uint32_t*)&Al[r0 * 56 + k0];
        uint32_t al1 = *(const uint32_t*)&Al[(r0 + 8) * 56 + k0];
        uint32_t al2 = *(const uint32_t*)&Al[r0 * 56 + k0 + 8];
        uint32_t al3 = *(const uint32_t*)&Al[(r0 + 8) * 56 + k0 + 8];
#pragma unroll
        for (int nt = 0; nt < 8; ++nt) {
            int nr = nt * 8 + g;
            uint32_t bh0 = *(const uint32_t*)&Bh[nr * 56 + k0];
            uint32_t bh1 = *(const uint32_t*)&Bh[nr * 56 + k0 + 8];
            uint32_t bl0 = *(const uint32_t*)&Bl[nr * 56 + k0];
            uint32_t bl1 = *(const uint32_t*)&Bl[nr * 56 + k0 + 8];
            MMA_BF16(d[nt], ah0, ah1, ah2, ah3, bh0, bh1);
            MMA_BF16(d[nt], ah0, ah1, ah2, ah3, bl0, bl1);
            MMA_BF16(d[nt], al0, al1, al2, al3, bh0, bh1);
        }
    }

#pragma unroll
    for (int nt = 0; nt < 8; ++nt) {
        int co = nt * 8 + tq * 2;
        int px = w * 16 + g;
        float bias0 = b1[co], bias1 = b1[co + 1];
#pragma unroll
        for (int h = 0; h < 2; ++h) {
            int m = px + h * 8;
            int dy = m >> 6, ox = m & 63;
            float v0 = fmaxf(d[nt][2 * h + 0] + bias0, 0.f);
            float v1 = fmaxf(d[nt][2 * h + 1] + bias1, 0.f);
            __nv_bfloat16 hv[2], lv[2];
            hv[0] = __float2bfloat16(v0);
            lv[0] = __float2bfloat16(v0 - __bfloat162float(hv[0]));
            hv[1] = __float2bfloat16(v1);
            lv[1] = __float2bfloat16(v1 - __bfloat162float(hv[1]));
            size_t o = (((size_t)bt * 4096) + (oy0 + dy) * 64 + ox) * 64 + co;
            *(uint32_t*)&g_f1h[o] = *(uint32_t*)hv;
            *(uint32_t*)&g_f1l[o] = *(uint32_t*)lv;
        }
    }
}

// ---------------------------------------------------------------------------
// conv2 via tensor cores, SOFTWARE-PIPELINED over 18 (tap,half) rounds:
// double-buffered dynamic smem + one-round register prefetch, 1 sync/round.
// ---------------------------------------------------------------------------
#define C2_A 5120              // 128*40 per plane per buffer
#define C2_B 2560              // 64*40
#define C2_BUF (2*C2_A + 2*C2_B)   // 15360 elems per buffer
#define CONV2_SMEM (2 * C2_BUF * 2)  // 61440 bytes

__global__ void __launch_bounds__(256, 2)
conv2_mma_kernel(const float* __restrict__ b2) {
    extern __shared__ __nv_bfloat16 smraw[];
    // per-buffer pointers: [buf][Ah | Al | Bh | Bl]
    int tid = threadIdx.x;
    int w = tid >> 5, lane = tid & 31;
    int g = lane >> 2, tq = lane & 3;
    int bx = blockIdx.x, bt = blockIdx.y;
    const __nv_bfloat16* f1h = g_f1h + (size_t)bt * 4096 * 64;
    const __nv_bfloat16* f1l = g_f1l + (size_t)bt * 4096 * 64;

    const int am0 = tid >> 2, ac = tid & 3;            // A: idx = tid (m,chunk)
    const int am1 = (tid + 256) >> 2;                  // A: idx = tid+256
    const int bn = tid >> 2, bc = tid & 3;             // B

    const uint4 zero4 = make_uint4(0u, 0u, 0u, 0u);
    uint4 ra0h, ra0l, ra1h, ra1l, rbh, rbl;

    // ---- loader: fetch stage s into registers ----
    auto load_stage = [&](int s) {
        int tap = s >> 1, half = s & 1;
        int kh = tap / 3, kw = tap - 3 * kh;
        int cb = half * 32;
        // A idx = tid
        {
            int dy = am0 >> 5, ox = am0 & 31;
            int iy = 2 * (bx * 4 + dy) + kh;
            int ix = 2 * ox + kw;
            if (iy < 64 && ix < 64) {
                size_t src = ((size_t)iy * 64 + ix) * 64 + cb + ac * 8;
                ra0h = *(const uint4*)&f1h[src];
                ra0l = *(const uint4*)&f1l[src];
            } else { ra0h = zero4; ra0l = zero4; }
        }
        // A idx = tid + 256
        {
            int dy = am1 >> 5, ox = am1 & 31;
            int iy = 2 * (bx * 4 + dy) + kh;
            int ix = 2 * ox + kw;
            if (iy < 64 && ix < 64) {
                size_t src = ((size_t)iy * 64 + ix) * 64 + cb + ac * 8;
                ra1h = *(const uint4*)&f1h[src];
                ra1l = *(const uint4*)&f1l[src];
            } else { ra1h = zero4; ra1l = zero4; }
        }
        // B
        {
            int src = tap * 4096 + bn * 64 + cb + bc * 8;
            rbh = *(const uint4*)&g_w2h[src];
            rbl = *(const uint4*)&g_w2l[src];
        }
    };
    auto store_stage = [&](int q) {
        __nv_bfloat16* Ah = smraw + (size_t)q * C2_BUF;
        __nv_bfloat16* Al = Ah + C2_A;
        __nv_bfloat16* Bh = Al + C2_A;
        __nv_bfloat16* Bl = Bh + C2_B;
        *(uint4*)&Ah[am0 * 40 + ac * 8] = ra0h;
        *(uint4*)&Al[am0 * 40 + ac * 8] = ra0l;
        *(uint4*)&Ah[am1 * 40 + ac * 8] = ra1h;
        *(uint4*)&Al[am1 * 40 + ac * 8] = ra1l;
        *(uint4*)&Bh[bn * 40 + bc * 8] = rbh;
        *(uint4*)&Bl[bn * 40 + bc * 8] = rbl;
    };

    float d[8][4] = {};

    load_stage(0);
    store_stage(0);
    load_stage(1);
    __syncthreads();

    int p = 0;
#pragma unroll 1
    for (int s = 0; s < 18; ++s) {
        if (s + 1 < 18) store_stage(p ^ 1);
        if (s + 2 < 18) load_stage(s + 2);

        const __nv_bfloat16* Ah = smraw + (size_t)p * C2_BUF;
        const __nv_bfloat16* Al = Ah + C2_A;
        const __nv_bfloat16* Bh = Al + C2_A;
        const __nv_bfloat16* Bl = Bh + C2_B;
#pragma unroll
        for (int ks = 0; ks < 2; ++ks) {
            int k0 = ks * 16 + tq * 2;
            int r0 = w * 16 + g;
            uint32_t ah0 = *(const uint32_t*)&Ah[r0 * 40 + k0];
            uint32_t ah1 = *(const uint32_t*)&Ah[(r0 + 8) * 40 + k0];
            uint32_t ah2 = *(const uint32_t*)&Ah[r0 * 40 + k0 + 8];
            uint32_t ah3 = *(const uint32_t*)&Ah[(r0 + 8) * 40 + k0 + 8];
            uint32_t al0 = *(const uint32_t*)&Al[r0 * 40 + k0];
            uint32_t al1 = *(const uint32_t*)&Al[(r0 + 8) * 40 + k0];
            uint32_t al2 = *(const uint32_t*)&Al[r0 * 40 + k0 + 8];
            uint32_t al3 = *(const uint32_t*)&Al[(r0 + 8) * 40 + k0 + 8];
#pragma unroll
            for (int nt = 0; nt < 8; ++nt) {
                int nr = nt * 8 + g;
                uint32_t bh0 = *(const uint32_t*)&Bh[nr * 40 + k0];
                uint32_t bh1 = *(const uint32_t*)&Bh[nr * 40 + k0 + 8];
                uint32_t bl0 = *(const uint32_t*)&Bl[nr * 40 + k0];
                uint32_t bl1 = *(const uint32_t*)&Bl[nr * 40 + k0 + 8];
                MMA_BF16(d[nt], ah0, ah1, ah2, ah3, bh0, bh1);
                MMA_BF16(d[nt], ah0, ah1, ah2, ah3, bl0, bl1);
                MMA_BF16(d[nt], al0, al1, al2, al3, bh0, bh1);
            }
        }
        __syncthreads();
        p ^= 1;
    }

    int oyb = bx * 4;
#pragma unroll
    for (int nt = 0; nt < 8; ++nt) {
        int co = nt * 8 + tq * 2;
        int px = w * 16 + g;
        float bias0 = b2[co], bias1 = b2[co + 1];
#pragma unroll
        for (int h = 0; h < 2; ++h) {
            int p2 = px + h * 8;
            int dy = p2 >> 5, ox = p2 & 31;
            size_t base = (((size_t)bt * 64 + co) * 32 + oyb + dy) * 32 + ox;
            g_f2[base]        = fmaxf(d[nt][2 * h + 0] + bias0, 0.f);
            g_f2[base + 1024] = fmaxf(d[nt][2 * h + 1] + bias1, 0.f);
        }
    }
}

// ---------------------------------------------------------------------------
__global__ void roi_kernel(const float* __restrict__ rois) {
    int r = blockIdx.x;
    __shared__ float ro[5];
    if (threadIdx.x < 5) ro[threadIdx.x] = rois[(size_t)r * 5 + threadIdx.x];
    __syncthreads();
    int bt = (int)ro[0];
    float x1 = ro[1] * 0.25f, y1 = ro[2] * 0.25f;
    float x2 = ro[3] * 0.25f, y2 = ro[4] * 0.25f;
    float bw = fmaxf(x2 - x1, 1.f) * 0.25f;
    float bh = fmaxf(y2 - y1, 1.f) * 0.25f;
    for (int idx = threadIdx.x; idx < 1024; idx += 256) {
        int c = idx >> 4, py = (idx >> 2) & 3, px = idx & 3;
        float sx = x1 + bw * (px + 0.5f);
        float sy = y1 + bh * (py + 0.5f);
        float x0f = fminf(fmaxf(floorf(sx), 0.f), 31.f);
        float y0f = fminf(fmaxf(floorf(sy), 0.f), 31.f);
        float lx = fminf(fmaxf(sx - x0f, 0.f), 1.f);
        float ly = fminf(fmaxf(sy - y0f, 0.f), 1.f);
        int x0 = (int)x0f, y0 = (int)y0f;
        int x1i = min(x0 + 1, 31), y1i = min(y0 + 1, 31);
        const float* f = &g_f2[((size_t)bt * 64 + c) * 1024];
        float v00 = f[y0 * 32 + x0];
        float v01 = f[y0 * 32 + x1i];
        float v10 = f[y1i * 32 + x0];
        float v11 = f[y1i * 32 + x1i];
        float val = v00 * (1.f - ly) * (1.f - lx) + v01 * (1.f - ly) * lx +
                    v10 * ly * (1.f - lx) + v11 * ly * lx;
        g_pool[(size_t)r * 1024 + idx] = val;
    }
}

// ---------------------------------------------------------------------------
__global__ void emb0_kernel(const float* __restrict__ sc,
                            const float* __restrict__ w,
                            const float* __restrict__ b) {
    int row = blockIdx.x, c = threadIdx.x;
    float x0 = sc[(size_t)row * 2], x1 = sc[(size_t)row * 2 + 1];
    float e = fmaf(w[c * 2], x0, fmaf(w[c * 2 + 1], x1, b[c]));
    g_emb1[(size_t)row * ND + c] = fmaxf(e, 0.f);
}

__global__ void rearr_kernel() {
    int i = blockIdx.x * 256 + threadIdx.x;
    int d = i & 255;
    int m = i >> 8;
    int n = m % NN;
    int t = (m / NN) % NT;
    int b = m / (NN * NT);
    float v = g_sttmp[i];
    __nv_bfloat16 h = __float2bfloat16(v);
    size_t o = ((size_t)t * NROW + b * NN + n) * ND + d;
    g_Oh[o] = h;
    g_Ol[o] = __float2bfloat16(v - __bfloat162float(h));
}

// ---------------------------------------------------------------------------
// Scalar pipelined NT GEMM (round 8, preamble only)
// ---------------------------------------------------------------------------
struct GemmArgs {
    const float* A1[12];
    const float* A2[12];
    const float* W[12];
    const float* Bias[12];
    float*       C[12];
    int          ldw[12];
    int lda1, lda2, ldc, K1, K2, relu;
};

__global__ void gemm_nt_kernel(GemmArgs g) {
    const int z = blockIdx.z;
    const float* __restrict__ A1 = g.A1[z];
    const float* __restrict__ A2 = g.A2[z];
    const float* __restrict__ W  = g.W[z];
    const float* __restrict__ Bv = g.Bias[z];
    float* __restrict__ C = g.C[z];
    const int ldw = g.ldw[z];
    const int m0 = blockIdx.x * 64, n0 = blockIdx.y * 64;
    __shared__ float As[2][16 * 68];
    __shared__ float Ws[2][16 * 68];
    const int tid = threadIdx.x;
    const int lr = tid >> 2, lc = (tid & 3) * 4;
    const int ty = tid >> 4, tx = tid & 15;
    float acc[4][4] = {};
    const int K = g.K1 + g.K2;
    const int niter = K >> 4;
    const float* wrow = W + (size_t)(n0 + lr) * ldw;

    float4 av, wv;
    {
        int col = lc;
        const float* ap = (col < g.K1)
            ? A1 + (size_t)(m0 + lr) * g.lda1 + col
            : A2 + (size_t)(m0 + lr) * g.lda2 + (col - g.K1);
        av = *(const float4*)ap;
        wv = *(const float4*)(wrow + col);
    }
    As[0][(lc + 0) * 68 + lr] = av.x; As[0][(lc + 1) * 68 + lr] = av.y;
    As[0][(lc + 2) * 68 + lr] = av.z; As[0][(lc + 3) * 68 + lr] = av.w;
    Ws[0][(lc + 0) * 68 + lr] = wv.x; Ws[0][(lc + 1) * 68 + lr] = wv.y;
    Ws[0][(lc + 2) * 68 + lr] = wv.z; Ws[0][(lc + 3) * 68 + lr] = wv.w;
    if (niter > 1) {
        int col = 16 + lc;
        const float* ap = (col < g.K1)
            ? A1 + (size_t)(m0 + lr) * g.lda1 + col
            : A2 + (size_t)(m0 + lr) * g.lda2 + (col - g.K1);
        av = *(const float4*)ap;
        wv = *(const float4*)(wrow + col);
    }
    __syncthreads();

    int p = 0;
#pragma unroll 1
    for (int i = 0; i < niter; ++i) {
        if (i + 1 < niter) {
            int q = p ^ 1;
            As[q][(lc + 0) * 68 + lr] = av.x; As[q][(lc + 1) * 68 + lr] = av.y;
            As[q][(lc + 2) * 68 + lr] = av.z; As[q][(lc + 3) * 68 + lr] = av.w;
            Ws[q][(lc + 0) * 68 + lr] = wv.x; Ws[q][(lc + 1) * 68 + lr] = wv.y;
            Ws[q][(lc + 2) * 68 + lr] = wv.z; Ws[q][(lc + 3) * 68 + lr] = wv.w;
        }
        if (i + 2 < niter) {
            int col = (i + 2) * 16 + lc;
            const float* ap = (col < g.K1)
                ? A1 + (size_t)(m0 + lr) * g.lda1 + col
                : A2 + (size_t)(m0 + lr) * g.lda2 + (col - g.K1);
            av = *(const float4*)ap;
            wv = *(const float4*)(wrow + col);
        }
#pragma unroll
        for (int k = 0; k < 16; ++k) {
            float4 a = *(const float4*)&As[p][k * 68 + ty * 4];
            float4 b = *(const float4*)&Ws[p][k * 68 + tx * 4];
            acc[0][0] += a.x * b.x; acc[0][1] += a.x * b.y; acc[0][2] += a.x * b.z; acc[0][3] += a.x * b.w;
            acc[1][0] += a.y * b.x; acc[1][1] += a.y * b.y; acc[1][2] += a.y * b.z; acc[1][3] += a.y * b.w;
            acc[2][0] += a.z * b.x; acc[2][1] += a.z * b.y; acc[2][2] += a.z * b.z; acc[2][3] += a.z * b.w;
            acc[3][0] += a.w * b.x; acc[3][1] += a.w * b.y; acc[3][2] += a.w * b.z; acc[3][3] += a.w * b.w;
        }
        __syncthreads();
        p ^= 1;
    }

    int n = n0 + tx * 4;
    float b0 = 0.f, b1 = 0.f, b2 = 0.f, b3 = 0.f;
    if (Bv) { b0 = Bv[n]; b1 = Bv[n + 1]; b2 = Bv[n + 2]; b3 = Bv[n + 3]; }
#pragma unroll
    for (int i = 0; i < 4; ++i) {
        float4 o;
        o.x = acc[i][0] + b0; o.y = acc[i][1] + b1;
        o.z = acc[i][2] + b2; o.w = acc[i][3] + b3;
        if (g.relu) {
            o.x = fmaxf(o.x, 0.f); o.y = fmaxf(o.y, 0.f);
            o.z = fmaxf(o.z, 0.f); o.w = fmaxf(o.w, 0.f);
        }
        *(float4*)(C + (size_t)(m0 + ty * 4 + i) * g.ldc + n) = o;
    }
}

// ---------------------------------------------------------------------------
// Tensor-core GEMM for rollout, SOFTWARE-PIPELINED (proven round 14)
// ---------------------------------------------------------------------------
struct GemmBfArgs {
    const __nv_bfloat16* Ah1[12];
    const __nv_bfloat16* Al1[12];
    const __nv_bfloat16* Ah2[12];
    const __nv_bfloat16* Al2[12];
    int whoff[12];
    const float* Bias[12];
    float* Cf[12];
    __nv_bfloat16* Ch[12];
    __nv_bfloat16* Cl[12];
    int ldw[12];
    int lda1, lda2, ldc, K1, K2, relu;
};

__global__ void gemm_bf16_kernel(GemmBfArgs g) {
    const int z = blockIdx.z;
    const __nv_bfloat16* __restrict__ A1h = g.Ah1[z];
    const __nv_bfloat16* __restrict__ A1l = g.Al1[z];
    const __nv_bfloat16* __restrict__ A2h = g.Ah2[z];
    const __nv_bfloat16* __restrict__ A2l = g.Al2[z];
    const __nv_bfloat16* __restrict__ Wh = g_wh + g.whoff[z];
    const __nv_bfloat16* __restrict__ Wl = g_wl + g.whoff[z];
    const float* __restrict__ Bv = g.Bias[z];
    float* __restrict__ Cf = g.Cf[z];
    __nv_bfloat16* __restrict__ Ch = g.Ch[z];
    __nv_bfloat16* __restrict__ Cl = g.Cl[z];
    const int ldw = g.ldw[z];
    const int m0 = blockIdx.x * 64, n0 = blockIdx.y * 64;

    __shared__ __nv_bfloat16 Ahs[2][64 * 40];
    __shared__ __nv_bfloat16 Als[2][64 * 40];
    __shared__ __nv_bfloat16 Bhs[2][64 * 40];
    __shared__ __nv_bfloat16 Bls[2][64 * 40];

    const int tid = threadIdx.x;
    const int wid = tid >> 5, lane = tid & 31;
    const int gq = lane >> 2, tq = lane & 3;
    const int wm = wid >> 1, wn = wid & 1;
    const int sm = tid >> 2, sc = tid & 3;

    float d[4][4] = {};
    const int K = g.K1 + g.K2;
    const int niter = K >> 5;

    uint4 rah, ral, rbh, rbl;

    {
        int col = sc * 8;
        const __nv_bfloat16 *ah, *al;
        if (col < g.K1) {
            ah = A1h + (size_t)(m0 + sm) * g.lda1 + col;
            al = A1l + (size_t)(m0 + sm) * g.lda1 + col;
        } else {
            ah = A2h + (size_t)(m0 + sm) * g.lda2 + (col - g.K1);
            al = A2l + (size_t)(m0 + sm) * g.lda2 + (col - g.K1);
        }
        rah = *(const uint4*)ah;
        ral = *(const uint4*)al;
        size_t src = (size_t)(n0 + sm) * ldw + col;
        rbh = *(const uint4*)&Wh[src];
        rbl = *(const uint4*)&Wl[src];
    }
    *(uint4*)&Ahs[0][sm * 40 + sc * 8] = rah;
    *(uint4*)&Als[0][sm * 40 + sc * 8] = ral;
    *(uint4*)&Bhs[0][sm * 40 + sc * 8] = rbh;
    *(uint4*)&Bls[0][sm * 40 + sc * 8] = rbl;
    if (niter > 1) {
        int col = 32 + sc * 8;
        const __nv_bfloat16 *ah, *al;
        if (col < g.K1) {
            ah = A1h + (size_t)(m0 + sm) * g.lda1 + col;
            al = A1l + (size_t)(m0 + sm) * g.lda1 + col;
        } else {
            ah = A2h + (size_t)(m0 + sm) * g.lda2 + (col - g.K1);
            al = A2l + (size_t)(m0 + sm) * g.lda2 + (col - g.K1);
        }
        rah = *(const uint4*)ah;
        ral = *(const uint4*)al;
        size_t src = (size_t)(n0 + sm) * ldw + col;
        rbh = *(const uint4*)&Wh[src];
        rbl = *(const uint4*)&Wl[src];
    }
    __syncthreads();

    int p = 0;
#pragma unroll 1
    for (int i = 0; i < niter; ++i) {
        if (i + 1 < niter) {
            int q = p ^ 1;
            *(uint4*)&Ahs[q][sm * 40 + sc * 8] = rah;
            *(uint4*)&Als[q][sm * 40 + sc * 8] = ral;
            *(uint4*)&Bhs[q][sm * 40 + sc * 8] = rbh;
            *(uint4*)&Bls[q][sm * 40 + sc * 8] = rbl;
        }
        if (i + 2 < niter) {
            int col = (i + 2) * 32 + sc * 8;
            const __nv_bfloat16 *ah, *al;
            if (col < g.K1) {
                ah = A1h + (size_t)(m0 + sm) * g.lda1 + col;
                al = A1l + (size_t)(m0 + sm) * g.lda1 + col;
            } else {
                ah = A2h + (size_t)(m0 + sm) * g.lda2 + (col - g.K1);
                al = A2l + (size_t)(m0 + sm) * g.lda2 + (col - g.K1);
            }
            rah = *(const uint4*)ah;
            ral = *(const uint4*)al;
            size_t src = (size_t)(n0 + sm) * ldw + col;
            rbh = *(const uint4*)&Wh[src];
            rbl = *(const uint4*)&Wl[src];
        }
#pragma unroll
        for (int ks = 0; ks < 2; ++ks) {
            int k0 = ks * 16 + tq * 2;
            int r0 = wm * 16 + gq;
            uint32_t ah0 = *(const uint32_t*)&Ahs[p][r0 * 40 + k0];
            uint32_t ah1 = *(const uint32_t*)&Ahs[p][(r0 + 8) * 40 + k0];
            uint32_t ah2 = *(const uint32_t*)&Ahs[p][r0 * 40 + k0 + 8];
            uint32_t ah3 = *(const uint32_t*)&Ahs[p][(r0 + 8) * 40 + k0 + 8];
            uint32_t al0 = *(const uint32_t*)&Als[p][r0 * 40 + k0];
            uint32_t al1 = *(const uint32_t*)&Als[p][(r0 + 8) * 40 + k0];
            uint32_t al2 = *(const uint32_t*)&Als[p][r0 * 40 + k0 + 8];
            uint32_t al3 = *(const uint32_t*)&Als[p][(r0 + 8) * 40 + k0 + 8];
#pragma unroll
            for (int nt = 0; nt < 4; ++nt) {
                int nr = wn * 32 + nt * 8 + gq;
                uint32_t bh0 = *(const uint32_t*)&Bhs[p][nr * 40 + k0];
                uint32_t bh1 = *(const uint32_t*)&Bhs[p][nr * 40 + k0 + 8];
                uint32_t bl0 = *(const uint32_t*)&Bls[p][nr * 40 + k0];
                uint32_t bl1 = *(const uint32_t*)&Bls[p][nr * 40 + k0 + 8];
                MMA_BF16(d[nt], ah0, ah1, ah2, ah3, bh0, bh1);
                MMA_BF16(d[nt], ah0, ah1, ah2, ah3, bl0, bl1);
                MMA_BF16(d[nt], al0, al1, al2, al3, bh0, bh1);
            }
        }
        __syncthreads();
        p ^= 1;
    }

#pragma unroll
    for (int nt = 0; nt < 4; ++nt) {
        int ncol = n0 + wn * 32 + nt * 8 + tq * 2;
        int row0 = m0 + wm * 16 + gq;
        float b0 = 0.f, b1 = 0.f;
        if (Bv) { b0 = Bv[ncol]; b1 = Bv[ncol + 1]; }
#pragma unroll
        for (int h = 0; h < 2; ++h) {
            int row = row0 + h * 8;
            float v0 = d[nt][2 * h + 0] + b0;
            float v1 = d[nt][2 * h + 1] + b1;
            if (g.relu) { v0 = fmaxf(v0, 0.f); v1 = fmaxf(v1, 0.f); }
            size_t o = (size_t)row * g.ldc + ncol;
            if (Cf) { Cf[o] = v0; Cf[o + 1] = v1; }
            if (Ch) {
                __nv_bfloat16 hv[2], lv[2];
                hv[0] = __float2bfloat16(v0);
                lv[0] = __float2bfloat16(v0 - __bfloat162float(hv[0]));
                hv[1] = __float2bfloat16(v1);
                lv[1] = __float2bfloat16(v1 - __bfloat162float(hv[1]));
                *(uint32_t*)&Ch[o] = *(uint32_t*)hv;
                *(uint32_t*)&Cl[o] = *(uint32_t*)lv;
            }
        }
    }
}

// ---------------------------------------------------------------------------
// masked relational sum: fp32 in, bf16 hi/lo out
// ---------------------------------------------------------------------------
struct MaskArgs {
    const float* coor[4];
    int cbs[4];
    int cns[4];
    const float* relb;
};

__global__ void mask_relsum_kernel(MaskArgs ma) {
    int b = blockIdx.x, k = blockIdx.y;
    __shared__ float cx[NN], cy[NN], rr[NN], cnt[NN];
    __shared__ int   mask[NN][NN];
    int tid = threadIdx.x;
    if (tid < NN) {
        const float* cp = ma.coor[k] + (size_t)b * ma.cbs[k] + tid * ma.cns[k];
        cx[tid] = cp[0];
        cy[tid] = cp[1];
        rr[tid] = g_r[b * NN + tid];
    }
    __syncthreads();
    if (tid < NN * NN) {
        int i = tid / NN, j = tid % NN;
        float dx = cx[i] - cx[j], dy = cy[i] - cy[j];
        float dist = sqrtf(dx * dx + dy * dy);
        mask[i][j] = (i != j) && (dist <= rr[i] + rr[j]);
    }
    __syncthreads();
    if (tid < NN) {
        int c = 0;
        for (int j = 0; j < NN; ++j) c += mask[tid][j];
        cnt[tid] = (float)c;
    }
    __syncthreads();
    int d = tid;
    float rb = ma.relb[k * ND + d];
    size_t base = (size_t)k * SD + (size_t)b * NN * ND;
    float vv[NN];
#pragma unroll
    for (int j = 0; j < NN; ++j) vv[j] = g_v[base + j * ND + d];
#pragma unroll
    for (int i = 0; i < NN; ++i) {
        float acc = g_selfd[base + i * ND + d] + cnt[i] * (g_u[base + i * ND + d] + rb);
#pragma unroll
        for (int j = 0; j < NN; ++j)
            if (mask[i][j]) acc += vv[j];
        __nv_bfloat16 h = __float2bfloat16(acc);
        g_th[base + i * ND + d] = h;
        g_tl[base + i * ND + d] = __float2bfloat16(acc - __bfloat162float(h));
    }
}

// ---------------------------------------------------------------------------
// agg_finish
// ---------------------------------------------------------------------------
__global__ void agg_finish_kernel(const float* __restrict__ aggb,
                                  const float* __restrict__ dw,
                                  const float* __restrict__ db,
                                  float* __restrict__ out,
                                  __nv_bfloat16* __restrict__ Psth,
                                  __nv_bfloat16* __restrict__ Pstl, int it) {
    int row = blockIdx.x, tid = threadIdx.x;
    size_t off = (size_t)row * ND + tid;
    float s = aggb[tid] + g_aggp[off] + g_aggp[SD + off] +
              g_aggp[2 * SD + off] + g_aggp[3 * SD + off];
    __nv_bfloat16 h = __float2bfloat16(s);
    Psth[off] = h;
    Pstl[off] = __float2bfloat16(s - __bfloat162float(h));
    float p0 = s * dw[tid];
    float p1 = s * dw[256 + tid];
    float p2 = s * dw[512 + tid];
    float p3 = s * dw[768 + tid];
#pragma unroll
    for (int o = 16; o > 0; o >>= 1) {
        p0 += __shfl_down_sync(0xffffffffu, p0, o);
        p1 += __shfl_down_sync(0xffffffffu, p1, o);
        p2 += __shfl_down_sync(0xffffffffu, p2, o);
        p3 += __shfl_down_sync(0xffffffffu, p3, o);
    }
    __shared__ float sw[8][4];
    int wid = tid >> 5, lane = tid & 31;
    if (lane == 0) { sw[wid][0] = p0; sw[wid][1] = p1; sw[wid][2] = p2; sw[wid][3] = p3; }
    __syncthreads();
    if (tid < 4) {
        float acc = db[tid];
#pragma unroll
        for (int w = 0; w < 8; ++w) acc += sw[w][tid];
        int b = row / NN, n = row % NN;
        out[(size_t)b * (NROLL * NN * 4) + it * (NN * 4) + n * 4 + tid] = acc;
    }
}

// ---------------------------------------------------------------------------
// Host launchers
// ---------------------------------------------------------------------------
static void launch_gemm(int numZ, int M, int K1, int K2,
                        const float* const* A1, int lda1,
                        const float* const* A2, int lda2,
                        const float* const* W, const int* ldw,
                        const float* const* Bias,
                        float* const* C, int ldc, int relu) {
    GemmArgs ga;
    for (int z = 0; z < numZ; ++z) {
        ga.A1[z] = A1[z];
        ga.A2[z] = A2 ? A2[z] : A1[z];
        ga.W[z] = W[z];
        ga.Bias[z] = Bias ? Bias[z] : nullptr;
        ga.C[z] = C[z];
        ga.ldw[z] = ldw[z];
    }
    for (int z = numZ; z < 12; ++z) {
        ga.A1[z] = ga.A1[0]; ga.A2[z] = ga.A2[0]; ga.W[z] = ga.W[0];
        ga.Bias[z] = nullptr; ga.C[z] = ga.C[0]; ga.ldw[z] = ga.ldw[0];
    }
    ga.lda1 = lda1; ga.lda2 = lda2; ga.ldc = ldc;
    ga.K1 = K1; ga.K2 = K2; ga.relu = relu;
    dim3 grid(M / 64, 4, numZ);
    gemm_nt_kernel<<<grid, 256>>>(ga);
}

struct BfSpec {
    const __nv_bfloat16 *ah1, *al1, *ah2, *al2;
    int whoff;
    const float* bias;
    float* cf;
    __nv_bfloat16 *ch, *cl;
    int ldw;
};

static void launch_gemm_bf(int numZ, const BfSpec* sp,
                           int lda1, int lda2, int ldc, int K1, int K2, int relu) {
    GemmBfArgs ga;
    for (int z = 0; z < numZ; ++z) {
        ga.Ah1[z] = sp[z].ah1; ga.Al1[z] = sp[z].al1;
        ga.Ah2[z] = sp[z].ah2 ? sp[z].ah2 : sp[z].ah1;
        ga.Al2[z] = sp[z].al2 ? sp[z].al2 : sp[z].al1;
        ga.whoff[z] = sp[z].whoff;
        ga.Bias[z] = sp[z].bias;
        ga.Cf[z] = sp[z].cf;
        ga.Ch[z] = sp[z].ch;
        ga.Cl[z] = sp[z].cl;
        ga.ldw[z] = sp[z].ldw;
    }
    for (int z = numZ; z < 12; ++z) {
        ga.Ah1[z] = ga.Ah1[0]; ga.Al1[z] = ga.Al1[0];
        ga.Ah2[z] = ga.Ah2[0]; ga.Al2[z] = ga.Al2[0];
        ga.whoff[z] = ga.whoff[0]; ga.Bias[z] = nullptr;
        ga.Cf[z] = ga.Cf[0]; ga.Ch[z] = ga.Ch[0]; ga.Cl[z] = ga.Cl[0];
        ga.ldw[z] = ga.ldw[0];
    }
    ga.lda1 = lda1; ga.lda2 = lda2; ga.ldc = ldc;
    ga.K1 = K1; ga.K2 = K2; ga.relu = relu;
    dim3 grid(NROW / 64, 4, numZ);
    gemm_bf16_kernel<<<grid, 256>>>(ga);
}

extern "C" void kernel_launch(void* const* d_in, const int* in_sizes, int n_in,
                              void* d_out, int out_size) {
    const float* x       = (const float*)d_in[0];
    const float* rois    = (const float*)d_in[1];
    const float* src     = (const float*)d_in[2];
    const float* w_conv1 = (const float*)d_in[3];
    const float* b_conv1 = (const float*)d_in[4];
    const float* w_conv2 = (const float*)d_in[5];
    const float* b_conv2 = (const float*)d_in[6];
    const float* fc0_w   = (const float*)d_in[7];
    const float* fc0_b   = (const float*)d_in[8];
    const float* fc0c_w  = (const float*)d_in[9];
    const float* fc0c_b  = (const float*)d_in[10];
    const float* fc1c_w  = (const float*)d_in[11];
    const float* fc1c_b  = (const float*)d_in[12];
    const float* red_w   = (const float*)d_in[13];
    const float* red_b   = (const float*)d_in[14];
    const float* g_self_w = (const float*)d_in[15];
    const float* g_self_b = (const float*)d_in[16];
    const float* g_rel_w  = (const float*)d_in[17];
    const float* g_rel_b  = (const float*)d_in[18];
    const float* g_aff_w  = (const float*)d_in[19];
    const float* g_aff_b  = (const float*)d_in[20];
    const float* g_out_w  = (const float*)d_in[21];
    const float* g_out_b  = (const float*)d_in[22];
    const float* agg_w   = (const float*)d_in[23];
    const float* agg_b   = (const float*)d_in[24];
    const float* dec_w   = (const float*)d_in[25];
    const float* dec_b   = (const float*)d_in[26];
    float* outp = (float*)d_out;

    float *pool, *obj, *emb1, *emb2, *sttmp, *selfd, *u, *v, *aggp;
    __nv_bfloat16 *Oh, *Ol, *Ph, *Pl, *th, *tl, *ah, *al, *csh, *csl;
    cudaGetSymbolAddress((void**)&pool,  g_pool);
    cudaGetSymbolAddress((void**)&obj,   g_obj);
    cudaGetSymbolAddress((void**)&emb1,  g_emb1);
    cudaGetSymbolAddress((void**)&emb2,  g_emb2);
    cudaGetSymbolAddress((void**)&sttmp, g_sttmp);
    cudaGetSymbolAddress((void**)&selfd, g_selfd);
    cudaGetSymbolAddress((void**)&u,     g_u);
    cudaGetSymbolAddress((void**)&v,     g_v);
    cudaGetSymbolAddress((void**)&aggp,  g_aggp);
    cudaGetSymbolAddress((void**)&Oh,    g_Oh);
    cudaGetSymbolAddress((void**)&Ol,    g_Ol);
    cudaGetSymbolAddress((void**)&Ph,    g_Ph);
    cudaGetSymbolAddress((void**)&Pl,    g_Pl);
    cudaGetSymbolAddress((void**)&th,    g_th);
    cudaGetSymbolAddress((void**)&tl,    g_tl);
    cudaGetSymbolAddress((void**)&ah,    g_ah);
    cudaGetSymbolAddress((void**)&al,    g_al);
    cudaGetSymbolAddress((void**)&csh,   g_csh);
    cudaGetSymbolAddress((void**)&csl,   g_csl);

    // ---- conversions ----
    cvt2_kernel<<<144, 256>>>(w_conv2);
    cvt1_kernel<<<3, 256>>>(w_conv1);
    xcvt_kernel<<<16384, 256>>>(x);
    {
        CvtArgs ca;
        ca.src[0] = g_self_w; ca.size[0] = 262144; ca.off[0] = OFF_SELF;
        ca.src[1] = g_rel_w;  ca.size[1] = 524288; ca.off[1] = OFF_REL;
        ca.src[2] = g_aff_w;  ca.size[2] = 262144; ca.off[2] = OFF_AFF;
        ca.src[3] = g_out_w;  ca.size[3] = 524288; ca.off[3] = OFF_OUT;
        ca.src[4] = agg_w;    ca.size[4] = 262144; ca.off[4] = OFF_AGG;
        cvt_kernel<<<dim3(512, 5), 256>>>(ca);
    }

    // ---- preamble ----
    r_kernel<<<3, 128>>>(rois);
    conv1_mma_kernel<<<dim3(32, NBT), 256>>>(b_conv1);
    cudaFuncSetAttribute(conv2_mma_kernel,
                         cudaFuncAttributeMaxDynamicSharedMemorySize, CONV2_SMEM);
    conv2_mma_kernel<<<dim3(8, NBT), 256, CONV2_SMEM>>>(b_conv2);
    roi_kernel<<<NROI, 256>>>(rois);
    emb0_kernel<<<NROI, 256>>>(src, fc0c_w, fc0c_b);

    {   // fc1c
        const float* A1[1] = { emb1 };
        const float* W[1] = { fc1c_w }; int ldw[1] = { 256 };
        const float* B[1] = { fc1c_b };
        float* C[1] = { emb2 };
        launch_gemm(1, NROI, 256, 0, A1, 256, nullptr, 0, W, ldw, B, C, ND, 1);
    }
    {   // fc0
        const float* A1[1] = { pool };
        const float* W[1] = { fc0_w }; int ldw[1] = { 1024 };
        const float* B[1] = { fc0_b };
        float* C[1] = { obj };
        launch_gemm(1, NROI, 1024, 0, A1, 1024, nullptr, 0, W, ldw, B, C, ND, 1);
    }
    {   // red
        const float* A1[1] = { obj };
        const float* A2[1] = { emb2 };
        const float* W[1] = { red_w }; int ldw[1] = { 512 };
        const float* B[1] = { red_b };
        float* C[1] = { sttmp };
        launch_gemm(1, NROI, 256, 256, A1, 256, A2, 256, W, ldw, B, C, ND, 1);
    }
    rearr_kernel<<<NROI, 256>>>();

    // ---- rollouts ----
    for (int it = 0; it < NROLL; ++it) {
        const __nv_bfloat16 *sth[4], *stl[4];
        MaskArgs ma;
        for (int k = 0; k < 4; ++k) {
            int idx = it + k;
            if (idx < 4) {
                sth[k] = Oh + (size_t)idx * SD;
                stl[k] = Ol + (size_t)idx * SD;
                ma.coor[k] = src + idx * (NN * 2);
                ma.cbs[k] = NT * NN * 2;
                ma.cns[k] = 2;
            } else {
                sth[k] = Ph + (size_t)(idx - 4) * SD;
                stl[k] = Pl + (size_t)(idx - 4) * SD;
                ma.coor[k] = outp + (idx - 4) * (NN * 4) + 2;
                ma.cbs[k] = NROLL * NN * 4;
                ma.cns[k] = 4;
            }
        }
        ma.relb = g_rel_b;

        {   // selfd / u / v
            BfSpec sp[12];
            for (int z = 0; z < 12; ++z) {
                int k = z & 3, kind = z >> 2;
                sp[z].ah1 = sth[k]; sp[z].al1 = stl[k];
                sp[z].ah2 = nullptr; sp[z].al2 = nullptr;
                sp[z].ch = nullptr; sp[z].cl = nullptr;
                if (kind == 0)      { sp[z].whoff = OFF_SELF + k * 65536;       sp[z].ldw = 256; sp[z].bias = g_self_b + k * 256; sp[z].cf = selfd + (size_t)k * SD; }
                else if (kind == 1) { sp[z].whoff = OFF_REL + k * 131072;       sp[z].ldw = 512; sp[z].bias = nullptr;            sp[z].cf = u + (size_t)k * SD; }
                else                { sp[z].whoff = OFF_REL + k * 131072 + 256; sp[z].ldw = 512; sp[z].bias = nullptr;            sp[z].cf = v + (size_t)k * SD; }
            }
            launch_gemm_bf(12, sp, 256, 256, ND, 256, 0, 0);
        }
        mask_relsum_kernel<<<dim3(NB, 4), 256>>>(ma);
        {   // aff
            BfSpec sp[4];
            for (int k = 0; k < 4; ++k) {
                sp[k].ah1 = th + (size_t)k * SD; sp[k].al1 = tl + (size_t)k * SD;
                sp[k].ah2 = nullptr; sp[k].al2 = nullptr;
                sp[k].whoff = OFF_AFF + k * 65536; sp[k].ldw = 256;
                sp[k].bias = g_aff_b + k * 256;
                sp[k].cf = nullptr;
                sp[k].ch = ah + (size_t)k * SD; sp[k].cl = al + (size_t)k * SD;
            }
            launch_gemm_bf(4, sp, 256, 256, ND, 256, 0, 1);
        }
        {   // out
            BfSpec sp[4];
            for (int k = 0; k < 4; ++k) {
                sp[k].ah1 = ah + (size_t)k * SD; sp[k].al1 = al + (size_t)k * SD;
                sp[k].ah2 = sth[k]; sp[k].al2 = stl[k];
                sp[k].whoff = OFF_OUT + k * 131072; sp[k].ldw = 512;
                sp[k].bias = g_out_b + k * 256;
                sp[k].cf = nullptr;
                sp[k].ch = csh + k * 256; sp[k].cl = csl + k * 256;
            }
            launch_gemm_bf(4, sp, 256, 256, 1024, 256, 256, 1);
        }
        {   // agg split-K x4
            BfSpec sp[4];
            for (int z = 0; z < 4; ++z) {
                sp[z].ah1 = csh + z * 256; sp[z].al1 = csl + z * 256;
                sp[z].ah2 = nullptr; sp[z].al2 = nullptr;
                sp[z].whoff = OFF_AGG + z * 256; sp[z].ldw = 1024;
                sp[z].bias = nullptr;
                sp[z].cf = aggp + (size_t)z * SD;
                sp[z].ch = nullptr; sp[z].cl = nullptr;
            }
            launch_gemm_bf(4, sp, 1024, 1024, ND, 256, 0, 0);
        }
        agg_finish_kernel<<<NROW, 256>>>(agg_b, dec_w, dec_b, outp,
                                         Ph + (size_t)it * SD, Pl + (size_t)it * SD, it);
    }

    (void)in_sizes; (void)n_in; (void)out_size;
}

// round 16
// speedup vs baseline: 1.5072x; 1.5072x over previous
#include <cuda_runtime.h>
#include <cuda_bf16.h>
#include <cstdint>

// ---------------------------------------------------------------------------
// Problem constants: B=64, T=4, N=6, IMG=128, CIN=3, VE=64, D=256, P=4, R=8
// ---------------------------------------------------------------------------
#define NB 64
#define NT 4
#define NN 6
#define NBT 256            // B*T
#define NROI 1536          // B*T*N
#define NROW 384           // B*N
#define ND 256
#define SD (NROW*ND)
#define NROLL 8

// ---------------------------------------------------------------------------
// Device scratch
// ---------------------------------------------------------------------------
__device__ __nv_bfloat16 g_x4h[(size_t)NBT * 128 * 128 * 4];
__device__ __nv_bfloat16 g_x4l[(size_t)NBT * 128 * 128 * 4];
__device__ __nv_bfloat16 g_w1h[9 * 64 * 4];
__device__ __nv_bfloat16 g_w1l[9 * 64 * 4];
__device__ __nv_bfloat16 g_f1h[(size_t)NBT * 64 * 64 * 64];   // channel-last
__device__ __nv_bfloat16 g_f1l[(size_t)NBT * 64 * 64 * 64];
__device__ __nv_bfloat16 g_w2h[9 * 64 * 64];
__device__ __nv_bfloat16 g_w2l[9 * 64 * 64];
__device__ float g_f2[(size_t)NBT * 64 * 32 * 32];
__device__ float g_pool [NROI * 1024];
__device__ float g_obj  [NROI * ND];
__device__ float g_emb1 [NROI * ND];
__device__ float g_emb2 [NROI * ND];
__device__ float g_sttmp[NROI * ND];
__device__ float g_selfd[4 * SD];
__device__ float g_u[4 * SD];
__device__ float g_v[4 * SD];
__device__ float g_aggp[4 * SD];
__device__ float g_r[NROW];
__device__ __nv_bfloat16 g_Oh[4 * SD],  g_Ol[4 * SD];
__device__ __nv_bfloat16 g_Ph[8 * SD],  g_Pl[8 * SD];
__device__ __nv_bfloat16 g_th[4 * SD],  g_tl[4 * SD];
__device__ __nv_bfloat16 g_ah[4 * SD],  g_al[4 * SD];
__device__ __nv_bfloat16 g_csh[NROW * 1024], g_csl[NROW * 1024];
#define OFF_SELF 0
#define OFF_REL  262144
#define OFF_AFF  786432
#define OFF_OUT  1048576
#define OFF_AGG  1572864
#define WTOTAL   1835008
__device__ __nv_bfloat16 g_wh[WTOTAL];
__device__ __nv_bfloat16 g_wl[WTOTAL];

// ---------------------------------------------------------------------------
// conversions
// ---------------------------------------------------------------------------
__global__ void cvt2_kernel(const float* __restrict__ w2) {
    int i = blockIdx.x * 256 + threadIdx.x;
    if (i >= 9 * 64 * 64) return;
    int ci = i & 63, n = (i >> 6) & 63, tap = i >> 12;
    float v = w2[(size_t)n * 576 + ci * 9 + tap];
    __nv_bfloat16 h = __float2bfloat16(v);
    g_w2h[i] = h;
    g_w2l[i] = __float2bfloat16(v - __bfloat162float(h));
}

__global__ void cvt1_kernel(const float* __restrict__ w1) {
    int i = blockIdx.x * 256 + threadIdx.x;
    if (i >= 576) return;
    int co = i % 64, tap = i / 64;
    __nv_bfloat16 hv[4], lv[4];
#pragma unroll
    for (int ci = 0; ci < 3; ++ci) {
        float v = w1[(size_t)co * 27 + ci * 9 + tap];
        hv[ci] = __float2bfloat16(v);
        lv[ci] = __float2bfloat16(v - __bfloat162float(hv[ci]));
    }
    hv[3] = __float2bfloat16(0.f);
    lv[3] = __float2bfloat16(0.f);
    *(uint2*)&g_w1h[(size_t)i * 4] = *(uint2*)hv;
    *(uint2*)&g_w1l[(size_t)i * 4] = *(uint2*)lv;
}

__global__ void xcvt_kernel(const float* __restrict__ x) {
    size_t p = (size_t)blockIdx.x * 256 + threadIdx.x;
    size_t bt = p >> 14, px = p & 16383;
    const float* xp = x + bt * 3 * 16384 + px;
    __nv_bfloat16 hv[4], lv[4];
#pragma unroll
    for (int ci = 0; ci < 3; ++ci) {
        float v = xp[(size_t)ci * 16384];
        hv[ci] = __float2bfloat16(v);
        lv[ci] = __float2bfloat16(v - __bfloat162float(hv[ci]));
    }
    hv[3] = __float2bfloat16(0.f);
    lv[3] = __float2bfloat16(0.f);
    *(uint2*)&g_x4h[p * 4] = *(uint2*)hv;
    *(uint2*)&g_x4l[p * 4] = *(uint2*)lv;
}

// vectorized: 4 elements per thread
struct CvtArgs { const float* src[5]; int size[5]; int off[5]; };
__global__ void cvt_kernel(CvtArgs c) {
    int seg = blockIdx.y;
    int i4 = (blockIdx.x * 256 + threadIdx.x) * 4;
    if (i4 >= c.size[seg]) return;
    float4 v = *(const float4*)(c.src[seg] + i4);
    __nv_bfloat16 hv[4], lv[4];
    hv[0] = __float2bfloat16(v.x); lv[0] = __float2bfloat16(v.x - __bfloat162float(hv[0]));
    hv[1] = __float2bfloat16(v.y); lv[1] = __float2bfloat16(v.y - __bfloat162float(hv[1]));
    hv[2] = __float2bfloat16(v.z); lv[2] = __float2bfloat16(v.z - __bfloat162float(hv[2]));
    hv[3] = __float2bfloat16(v.w); lv[3] = __float2bfloat16(v.w - __bfloat162float(hv[3]));
    *(uint2*)&g_wh[c.off[seg] + i4] = *(uint2*)hv;
    *(uint2*)&g_wl[c.off[seg] + i4] = *(uint2*)lv;
}

// ---------------------------------------------------------------------------
__global__ void r_kernel(const float* __restrict__ rois) {
    int i = blockIdx.x * 128 + threadIdx.x;
    if (i >= NROW) return;
    int b = i / NN, n = i % NN;
    float s = 0.f;
    for (int t = 0; t < NT; ++t) {
        const float* ro = rois + (size_t)(((b * NT + t) * NN) + n) * 5;
        s += ((ro[4] - ro[2]) * 0.5f + (ro[3] - ro[1]) * 0.5f) * 0.5f;
    }
    g_r[i] = s * 0.25f;
}

// ---------------------------------------------------------------------------
#define MMA_BF16(d, a0, a1, a2, a3, b0, b1)                                    \
    asm volatile(                                                              \
        "mma.sync.aligned.m16n8k16.row.col.f32.bf16.bf16.f32 "                \
        "{%0,%1,%2,%3},{%4,%5,%6,%7},{%8,%9},{%0,%1,%2,%3};"                  \
        : "+f"(d[0]), "+f"(d[1]), "+f"(d[2]), "+f"(d[3])                       \
        : "r"(a0), "r"(a1), "r"(a2), "r"(a3), "r"(b0), "r"(b1))

// ---------------------------------------------------------------------------
// conv1 via tensor cores (proven round 11)
// ---------------------------------------------------------------------------
__global__ void conv1_mma_kernel(const float* __restrict__ b1) {
    __shared__ __nv_bfloat16 Ah[128 * 56];
    __shared__ __nv_bfloat16 Al[128 * 56];
    __shared__ __nv_bfloat16 Bh[64 * 56];
    __shared__ __nv_bfloat16 Bl[64 * 56];

    int tid = threadIdx.x;
    int w = tid >> 5, lane = tid & 31;
    int g = lane >> 2, tq = lane & 3;
    int bx = blockIdx.x, bt = blockIdx.y;
    int oy0 = bx * 2;
    const __nv_bfloat16* xh = g_x4h + (size_t)bt * 16384 * 4;
    const __nv_bfloat16* xl = g_x4l + (size_t)bt * 16384 * 4;

    {
        uint4 z = make_uint4(0u, 0u, 0u, 0u);
        uint4* a4h = (uint4*)Ah; uint4* a4l = (uint4*)Al;
        for (int i = tid; i < 896; i += 256) { a4h[i] = z; a4l[i] = z; }
        uint4* b4h = (uint4*)Bh; uint4* b4l = (uint4*)Bl;
        for (int i = tid; i < 448; i += 256) { b4h[i] = z; b4l[i] = z; }
    }
    __syncthreads();

    for (int idx = tid; idx < 1152; idx += 256) {
        int t9 = idx >> 7, m = idx & 127;
        int kh = t9 / 3, kw = t9 - 3 * kh;
        int dy = m >> 6, ox = m & 63;
        int iy = 2 * (oy0 + dy) + kh;
        int ix = 2 * ox + kw;
        if (iy < 128 && ix < 128) {
            size_t src = ((size_t)iy * 128 + ix) * 4;
            *(uint2*)&Ah[m * 56 + t9 * 4] = *(const uint2*)&xh[src];
            *(uint2*)&Al[m * 56 + t9 * 4] = *(const uint2*)&xl[src];
        }
    }
    for (int idx = tid; idx < 576; idx += 256) {
        int t9 = idx / 64, co = idx % 64;
        *(uint2*)&Bh[co * 56 + t9 * 4] = *(const uint2*)&g_w1h[(size_t)idx * 4];
        *(uint2*)&Bl[co * 56 + t9 * 4] = *(const uint2*)&g_w1l[(size_t)idx * 4];
    }
    __syncthreads();

    float d[8][4] = {};
#pragma unroll
    for (int ks = 0; ks < 3; ++ks) {
        int k0 = ks * 16 + tq * 2;
        int r0 = w * 16 + g;
        uint32_t ah0 = *(const uint32_t*)&Ah[r0 * 56 + k0];
        uint32_t ah1 = *(const uint32_t*)&Ah[(r0 + 8) * 56 + k0];
        uint32_t ah2 = *(const uint32_t*)&Ah[r0 * 56 + k0 + 8];
        uint32_t ah3 = *(const uint32_t*)&Ah[(r0 + 8) * 56 + k0 + 8];
        uint32_t al0 = *(const uint32_t*)&Al[r0 * 56 + k0];
        uint32_t al1 = *(const uint32_t*)&Al[(r0 + 8) * 56 + k0];
        uint32_t al2 = *(const uint32_t*)&Al[r0 * 56 + k0 + 8];
        uint32_t al3 = *(const uint32_t*)&Al[(r0 + 8) * 56 + k0 + 8];
#pragma unroll
        for (int nt = 0; nt < 8; ++nt) {
            int nr = nt * 8 + g;
            uint32_t bh0 = *(const uint32_t*)&Bh[nr * 56 + k0];
            uint32_t bh1 = *(const uint32_t*)&Bh[nr * 56 + k0 + 8];
            uint32_t bl0 = *(const uint32_t*)&Bl[nr * 56 + k0];
            uint32_t bl1 = *(const uint32_t*)&Bl[nr * 56 + k0 + 8];
            MMA_BF16(d[nt], ah0, ah1, ah2, ah3, bh0, bh1);
            MMA_BF16(d[nt], ah0, ah1, ah2, ah3, bl0, bl1);
            MMA_BF16(d[nt], al0, al1, al2, al3, bh0, bh1);
        }
    }

#pragma unroll
    for (int nt = 0; nt < 8; ++nt) {
        int co = nt * 8 + tq * 2;
        int px = w * 16 + g;
        float bias0 = b1[co], bias1 = b1[co + 1];
#pragma unroll
        for (int h = 0; h < 2; ++h) {
            int m = px + h * 8;
            int dy = m >> 6, ox = m & 63;
            float v0 = fmaxf(d[nt][2 * h + 0] + bias0, 0.f);
            float v1 = fmaxf(d[nt][2 * h + 1] + bias1, 0.f);
            __nv_bfloat16 hv[2], lv[2];
            hv[0] = __float2bfloat16(v0);
            lv[0] = __float2bfloat16(v0 - __bfloat162float(hv[0]));
            hv[1] = __float2bfloat16(v1);
            lv[1] = __float2bfloat16(v1 - __bfloat162float(hv[1]));
            size_t o = (((size_t)bt * 4096) + (oy0 + dy) * 64 + ox) * 64 + co;
            *(uint32_t*)&g_f1h[o] = *(uint32_t*)hv;
            *(uint32_t*)&g_f1l[o] = *(uint32_t*)lv;
        }
    }
}

// ---------------------------------------------------------------------------
// conv2 via tensor cores (proven rounds 7/11/13/14: per-tap restage)
// ---------------------------------------------------------------------------
__global__ void conv2_mma_kernel(const float* __restrict__ b2) {
    __shared__ __nv_bfloat16 Ah[128 * 40];
    __shared__ __nv_bfloat16 Al[128 * 40];
    __shared__ __nv_bfloat16 Bh[64 * 40];
    __shared__ __nv_bfloat16 Bl[64 * 40];

    int tid = threadIdx.x;
    int w = tid >> 5, lane = tid & 31;
    int g = lane >> 2, tq = lane & 3;
    int bx = blockIdx.x, bt = blockIdx.y;
    const __nv_bfloat16* f1h = g_f1h + (size_t)bt * 4096 * 64;
    const __nv_bfloat16* f1l = g_f1l + (size_t)bt * 4096 * 64;

    float d[8][4] = {};
    const uint4 zero4 = make_uint4(0u, 0u, 0u, 0u);

#pragma unroll 1
    for (int tap = 0; tap < 9; ++tap) {
        int kh = tap / 3, kw = tap % 3;
#pragma unroll 1
        for (int half = 0; half < 2; ++half) {
            int cb = half * 32;
            __syncthreads();
            for (int idx = tid; idx < 512; idx += 256) {
                int m = idx >> 2, c = idx & 3;
                int dy = m >> 5, ox = m & 31;
                int iy = 2 * (bx * 4 + dy) + kh;
                int ix = 2 * ox + kw;
                uint4 hv = zero4, lv = zero4;
                if (iy < 64 && ix < 64) {
                    size_t src = ((size_t)iy * 64 + ix) * 64 + cb + c * 8;
                    hv = *(const uint4*)&f1h[src];
                    lv = *(const uint4*)&f1l[src];
                }
                *(uint4*)&Ah[m * 40 + c * 8] = hv;
                *(uint4*)&Al[m * 40 + c * 8] = lv;
            }
            {
                int n = tid >> 2, c = tid & 3;
                int src = tap * 4096 + n * 64 + cb + c * 8;
                *(uint4*)&Bh[n * 40 + c * 8] = *(const uint4*)&g_w2h[src];
                *(uint4*)&Bl[n * 40 + c * 8] = *(const uint4*)&g_w2l[src];
            }
            __syncthreads();
#pragma unroll
            for (int ks = 0; ks < 2; ++ks) {
                int k0 = ks * 16 + tq * 2;
                int r0 = w * 16 + g;
                uint32_t ah0 = *(const uint32_t*)&Ah[r0 * 40 + k0];
                uint32_t ah1 = *(const uint32_t*)&Ah[(r0 + 8) * 40 + k0];
                uint32_t ah2 = *(const uint32_t*)&Ah[r0 * 40 + k0 + 8];
                uint32_t ah3 = *(const uint32_t*)&Ah[(r0 + 8) * 40 + k0 + 8];
                uint32_t al0 = *(const uint32_t*)&Al[r0 * 40 + k0];
                uint32_t al1 = *(const uint32_t*)&Al[(r0 + 8) * 40 + k0];
                uint32_t al2 = *(const uint32_t*)&Al[r0 * 40 + k0 + 8];
                uint32_t al3 = *(const uint32_t*)&Al[(r0 + 8) * 40 + k0 + 8];
#pragma unroll
                for (int nt = 0; nt < 8; ++nt) {
                    int nr = nt * 8 + g;
                    uint32_t bh0 = *(const uint32_t*)&Bh[nr * 40 + k0];
                    uint32_t bh1 = *(const uint32_t*)&Bh[nr * 40 + k0 + 8];
                    uint32_t bl0 = *(const uint32_t*)&Bl[nr * 40 + k0];
                    uint32_t bl1 = *(const uint32_t*)&Bl[nr * 40 + k0 + 8];
                    MMA_BF16(d[nt], ah0, ah1, ah2, ah3, bh0, bh1);
                    MMA_BF16(d[nt], ah0, ah1, ah2, ah3, bl0, bl1);
                    MMA_BF16(d[nt], al0, al1, al2, al3, bh0, bh1);
                }
            }
        }
    }

    int oyb = bx * 4;
#pragma unroll
    for (int nt = 0; nt < 8; ++nt) {
        int co = nt * 8 + tq * 2;
        int px = w * 16 + g;
        float bias0 = b2[co], bias1 = b2[co + 1];
#pragma unroll
        for (int h = 0; h < 2; ++h) {
            int p = px + h * 8;
            int dy = p >> 5, ox = p & 31;
            size_t base = (((size_t)bt * 64 + co) * 32 + oyb + dy) * 32 + ox;
            g_f2[base]        = fmaxf(d[nt][2 * h + 0] + bias0, 0.f);
            g_f2[base + 1024] = fmaxf(d[nt][2 * h + 1] + bias1, 0.f);
        }
    }
}

// ---------------------------------------------------------------------------
__global__ void roi_kernel(const float* __restrict__ rois) {
    int r = blockIdx.x;
    __shared__ float ro[5];
    if (threadIdx.x < 5) ro[threadIdx.x] = rois[(size_t)r * 5 + threadIdx.x];
    __syncthreads();
    int bt = (int)ro[0];
    float x1 = ro[1] * 0.25f, y1 = ro[2] * 0.25f;
    float x2 = ro[3] * 0.25f, y2 = ro[4] * 0.25f;
    float bw = fmaxf(x2 - x1, 1.f) * 0.25f;
    float bh = fmaxf(y2 - y1, 1.f) * 0.25f;
    for (int idx = threadIdx.x; idx < 1024; idx += 256) {
        int c = idx >> 4, py = (idx >> 2) & 3, px = idx & 3;
        float sx = x1 + bw * (px + 0.5f);
        float sy = y1 + bh * (py + 0.5f);
        float x0f = fminf(fmaxf(floorf(sx), 0.f), 31.f);
        float y0f = fminf(fmaxf(floorf(sy), 0.f), 31.f);
        float lx = fminf(fmaxf(sx - x0f, 0.f), 1.f);
        float ly = fminf(fmaxf(sy - y0f, 0.f), 1.f);
        int x0 = (int)x0f, y0 = (int)y0f;
        int x1i = min(x0 + 1, 31), y1i = min(y0 + 1, 31);
        const float* f = &g_f2[((size_t)bt * 64 + c) * 1024];
        float v00 = f[y0 * 32 + x0];
        float v01 = f[y0 * 32 + x1i];
        float v10 = f[y1i * 32 + x0];
        float v11 = f[y1i * 32 + x1i];
        float val = v00 * (1.f - ly) * (1.f - lx) + v01 * (1.f - ly) * lx +
                    v10 * ly * (1.f - lx) + v11 * ly * lx;
        g_pool[(size_t)r * 1024 + idx] = val;
    }
}

// ---------------------------------------------------------------------------
__global__ void emb0_kernel(const float* __restrict__ sc,
                            const float* __restrict__ w,
                            const float* __restrict__ b) {
    int row = blockIdx.x, c = threadIdx.x;
    float x0 = sc[(size_t)row * 2], x1 = sc[(size_t)row * 2 + 1];
    float e = fmaf(w[c * 2], x0, fmaf(w[c * 2 + 1], x1, b[c]));
    g_emb1[(size_t)row * ND + c] = fmaxf(e, 0.f);
}

__global__ void rearr_kernel() {
    int i = blockIdx.x * 256 + threadIdx.x;
    int d = i & 255;
    int m = i >> 8;
    int n = m % NN;
    int t = (m / NN) % NT;
    int b = m / (NN * NT);
    float v = g_sttmp[i];
    __nv_bfloat16 h = __float2bfloat16(v);
    size_t o = ((size_t)t * NROW + b * NN + n) * ND + d;
    g_Oh[o] = h;
    g_Ol[o] = __float2bfloat16(v - __bfloat162float(h));
}

// ---------------------------------------------------------------------------
// Scalar pipelined NT GEMM (round 8, preamble only)
// ---------------------------------------------------------------------------
struct GemmArgs {
    const float* A1[12];
    const float* A2[12];
    const float* W[12];
    const float* Bias[12];
    float*       C[12];
    int          ldw[12];
    int lda1, lda2, ldc, K1, K2, relu;
};

__global__ void gemm_nt_kernel(GemmArgs g) {
    const int z = blockIdx.z;
    const float* __restrict__ A1 = g.A1[z];
    const float* __restrict__ A2 = g.A2[z];
    const float* __restrict__ W  = g.W[z];
    const float* __restrict__ Bv = g.Bias[z];
    float* __restrict__ C = g.C[z];
    const int ldw = g.ldw[z];
    const int m0 = blockIdx.x * 64, n0 = blockIdx.y * 64;
    __shared__ float As[2][16 * 68];
    __shared__ float Ws[2][16 * 68];
    const int tid = threadIdx.x;
    const int lr = tid >> 2, lc = (tid & 3) * 4;
    const int ty = tid >> 4, tx = tid & 15;
    float acc[4][4] = {};
    const int K = g.K1 + g.K2;
    const int niter = K >> 4;
    const float* wrow = W + (size_t)(n0 + lr) * ldw;

    float4 av, wv;
    {
        int col = lc;
        const float* ap = (col < g.K1)
            ? A1 + (size_t)(m0 + lr) * g.lda1 + col
            : A2 + (size_t)(m0 + lr) * g.lda2 + (col - g.K1);
        av = *(const float4*)ap;
        wv = *(const float4*)(wrow + col);
    }
    As[0][(lc + 0) * 68 + lr] = av.x; As[0][(lc + 1) * 68 + lr] = av.y;
    As[0][(lc + 2) * 68 + lr] = av.z; As[0][(lc + 3) * 68 + lr] = av.w;
    Ws[0][(lc + 0) * 68 + lr] = wv.x; Ws[0][(lc + 1) * 68 + lr] = wv.y;
    Ws[0][(lc + 2) * 68 + lr] = wv.z; Ws[0][(lc + 3) * 68 + lr] = wv.w;
    if (niter > 1) {
        int col = 16 + lc;
        const float* ap = (col < g.K1)
            ? A1 + (size_t)(m0 + lr) * g.lda1 + col
            : A2 + (size_t)(m0 + lr) * g.lda2 + (col - g.K1);
        av = *(const float4*)ap;
        wv = *(const float4*)(wrow + col);
    }
    __syncthreads();

    int p = 0;
#pragma unroll 1
    for (int i = 0; i < niter; ++i) {
        if (i + 1 < niter) {
            int q = p ^ 1;
            As[q][(lc + 0) * 68 + lr] = av.x; As[q][(lc + 1) * 68 + lr] = av.y;
            As[q][(lc + 2) * 68 + lr] = av.z; As[q][(lc + 3) * 68 + lr] = av.w;
            Ws[q][(lc + 0) * 68 + lr] = wv.x; Ws[q][(lc + 1) * 68 + lr] = wv.y;
            Ws[q][(lc + 2) * 68 + lr] = wv.z; Ws[q][(lc + 3) * 68 + lr] = wv.w;
        }
        if (i + 2 < niter) {
            int col = (i + 2) * 16 + lc;
            const float* ap = (col < g.K1)
                ? A1 + (size_t)(m0 + lr) * g.lda1 + col
                : A2 + (size_t)(m0 + lr) * g.lda2 + (col - g.K1);
            av = *(const float4*)ap;
            wv = *(const float4*)(wrow + col);
        }
#pragma unroll
        for (int k = 0; k < 16; ++k) {
            float4 a = *(const float4*)&As[p][k * 68 + ty * 4];
            float4 b = *(const float4*)&Ws[p][k * 68 + tx * 4];
            acc[0][0] += a.x * b.x; acc[0][1] += a.x * b.y; acc[0][2] += a.x * b.z; acc[0][3] += a.x * b.w;
            acc[1][0] += a.y * b.x; acc[1][1] += a.y * b.y; acc[1][2] += a.y * b.z; acc[1][3] += a.y * b.w;
            acc[2][0] += a.z * b.x; acc[2][1] += a.z * b.y; acc[2][2] += a.z * b.z; acc[2][3] += a.z * b.w;
            acc[3][0] += a.w * b.x; acc[3][1] += a.w * b.y; acc[3][2] += a.w * b.z; acc[3][3] += a.w * b.w;
        }
        if (i + 1 < niter) __syncthreads();
        p ^= 1;
    }

    int n = n0 + tx * 4;
    float b0 = 0.f, b1 = 0.f, b2 = 0.f, b3 = 0.f;
    if (Bv) { b0 = Bv[n]; b1 = Bv[n + 1]; b2 = Bv[n + 2]; b3 = Bv[n + 3]; }
#pragma unroll
    for (int i = 0; i < 4; ++i) {
        float4 o;
        o.x = acc[i][0] + b0; o.y = acc[i][1] + b1;
        o.z = acc[i][2] + b2; o.w = acc[i][3] + b3;
        if (g.relu) {
            o.x = fmaxf(o.x, 0.f); o.y = fmaxf(o.y, 0.f);
            o.z = fmaxf(o.z, 0.f); o.w = fmaxf(o.w, 0.f);
        }
        *(float4*)(C + (size_t)(m0 + ty * 4 + i) * g.ldc + n) = o;
    }
}

// ---------------------------------------------------------------------------
// Tensor-core GEMM for rollout, SOFTWARE-PIPELINED (proven round 14)
// ---------------------------------------------------------------------------
struct GemmBfArgs {
    const __nv_bfloat16* Ah1[12];
    const __nv_bfloat16* Al1[12];
    const __nv_bfloat16* Ah2[12];
    const __nv_bfloat16* Al2[12];
    int whoff[12];
    const float* Bias[12];
    float* Cf[12];
    __nv_bfloat16* Ch[12];
    __nv_bfloat16* Cl[12];
    int ldw[12];
    int lda1, lda2, ldc, K1, K2, relu;
};

__global__ void gemm_bf16_kernel(GemmBfArgs g) {
    const int z = blockIdx.z;
    const __nv_bfloat16* __restrict__ A1h = g.Ah1[z];
    const __nv_bfloat16* __restrict__ A1l = g.Al1[z];
    const __nv_bfloat16* __restrict__ A2h = g.Ah2[z];
    const __nv_bfloat16* __restrict__ A2l = g.Al2[z];
    const __nv_bfloat16* __restrict__ Wh = g_wh + g.whoff[z];
    const __nv_bfloat16* __restrict__ Wl = g_wl + g.whoff[z];
    const float* __restrict__ Bv = g.Bias[z];
    float* __restrict__ Cf = g.Cf[z];
    __nv_bfloat16* __restrict__ Ch = g.Ch[z];
    __nv_bfloat16* __restrict__ Cl = g.Cl[z];
    const int ldw = g.ldw[z];
    const int m0 = blockIdx.x * 64, n0 = blockIdx.y * 64;

    __shared__ __nv_bfloat16 Ahs[2][64 * 40];
    __shared__ __nv_bfloat16 Als[2][64 * 40];
    __shared__ __nv_bfloat16 Bhs[2][64 * 40];
    __shared__ __nv_bfloat16 Bls[2][64 * 40];

    const int tid = threadIdx.x;
    const int wid = tid >> 5, lane = tid & 31;
    const int gq = lane >> 2, tq = lane & 3;
    const int wm = wid >> 1, wn = wid & 1;
    const int sm = tid >> 2, sc = tid & 3;

    float d[4][4] = {};
    const int K = g.K1 + g.K2;
    const int niter = K >> 5;

    uint4 rah, ral, rbh, rbl;

    {
        int col = sc * 8;
        const __nv_bfloat16 *ah, *al;
        if (col < g.K1) {
            ah = A1h + (size_t)(m0 + sm) * g.lda1 + col;
            al = A1l + (size_t)(m0 + sm) * g.lda1 + col;
        } else {
            ah = A2h + (size_t)(m0 + sm) * g.lda2 + (col - g.K1);
            al = A2l + (size_t)(m0 + sm) * g.lda2 + (col - g.K1);
        }
        rah = *(const uint4*)ah;
        ral = *(const uint4*)al;
        size_t src = (size_t)(n0 + sm) * ldw + col;
        rbh = *(const uint4*)&Wh[src];
        rbl = *(const uint4*)&Wl[src];
    }
    *(uint4*)&Ahs[0][sm * 40 + sc * 8] = rah;
    *(uint4*)&Als[0][sm * 40 + sc * 8] = ral;
    *(uint4*)&Bhs[0][sm * 40 + sc * 8] = rbh;
    *(uint4*)&Bls[0][sm * 40 + sc * 8] = rbl;
    if (niter > 1) {
        int col = 32 + sc * 8;
        const __nv_bfloat16 *ah, *al;
        if (col < g.K1) {
            ah = A1h + (size_t)(m0 + sm) * g.lda1 + col;
            al = A1l + (size_t)(m0 + sm) * g.lda1 + col;
        } else {
            ah = A2h + (size_t)(m0 + sm) * g.lda2 + (col - g.K1);
            al = A2l + (size_t)(m0 + sm) * g.lda2 + (col - g.K1);
        }
        rah = *(const uint4*)ah;
        ral = *(const uint4*)al;
        size_t src = (size_t)(n0 + sm) * ldw + col;
        rbh = *(const uint4*)&Wh[src];
        rbl = *(const uint4*)&Wl[src];
    }
    __syncthreads();

    int p = 0;
#pragma unroll 1
    for (int i = 0; i < niter; ++i) {
        if (i + 1 < niter) {
            int q = p ^ 1;
            *(uint4*)&Ahs[q][sm * 40 + sc * 8] = rah;
            *(uint4*)&Als[q][sm * 40 + sc * 8] = ral;
            *(uint4*)&Bhs[q][sm * 40 + sc * 8] = rbh;
            *(uint4*)&Bls[q][sm * 40 + sc * 8] = rbl;
        }
        if (i + 2 < niter) {
            int col = (i + 2) * 32 + sc * 8;
            const __nv_bfloat16 *ah, *al;
            if (col < g.K1) {
                ah = A1h + (size_t)(m0 + sm) * g.lda1 + col;
                al = A1l + (size_t)(m0 + sm) * g.lda1 + col;
            } else {
                ah = A2h + (size_t)(m0 + sm) * g.lda2 + (col - g.K1);
                al = A2l + (size_t)(m0 + sm) * g.lda2 + (col - g.K1);
            }
            rah = *(const uint4*)ah;
            ral = *(const uint4*)al;
            size_t src = (size_t)(n0 + sm) * ldw + col;
            rbh = *(const uint4*)&Wh[src];
            rbl = *(const uint4*)&Wl[src];
        }
#pragma unroll
        for (int ks = 0; ks < 2; ++ks) {
            int k0 = ks * 16 + tq * 2;
            int r0 = wm * 16 + gq;
            uint32_t ah0 = *(const uint32_t*)&Ahs[p][r0 * 40 + k0];
            uint32_t ah1 = *(const uint32_t*)&Ahs[p][(r0 + 8) * 40 + k0];
            uint32_t ah2 = *(const uint32_t*)&Ahs[p][r0 * 40 + k0 + 8];
            uint32_t ah3 = *(const uint32_t*)&Ahs[p][(r0 + 8) * 40 + k0 + 8];
            uint32_t al0 = *(const uint32_t*)&Als[p][r0 * 40 + k0];
            uint32_t al1 = *(const uint32_t*)&Als[p][(r0 + 8) * 40 + k0];
            uint32_t al2 = *(const uint32_t*)&Als[p][r0 * 40 + k0 + 8];
            uint32_t al3 = *(const uint32_t*)&Als[p][(r0 + 8) * 40 + k0 + 8];
#pragma unroll
            for (int nt = 0; nt < 4; ++nt) {
                int nr = wn * 32 + nt * 8 + gq;
                uint32_t bh0 = *(const uint32_t*)&Bhs[p][nr * 40 + k0];
                uint32_t bh1 = *(const uint32_t*)&Bhs[p][nr * 40 + k0 + 8];
                uint32_t bl0 = *(const uint32_t*)&Bls[p][nr * 40 + k0];
                uint32_t bl1 = *(const uint32_t*)&Bls[p][nr * 40 + k0 + 8];
                MMA_BF16(d[nt], ah0, ah1, ah2, ah3, bh0, bh1);
                MMA_BF16(d[nt], ah0, ah1, ah2, ah3, bl0, bl1);
                MMA_BF16(d[nt], al0, al1, al2, al3, bh0, bh1);
            }
        }
        if (i + 1 < niter) __syncthreads();
        p ^= 1;
    }

#pragma unroll
    for (int nt = 0; nt < 4; ++nt) {
        int ncol = n0 + wn * 32 + nt * 8 + tq * 2;
        int row0 = m0 + wm * 16 + gq;
        float b0 = 0.f, b1 = 0.f;
        if (Bv) { b0 = Bv[ncol]; b1 = Bv[ncol + 1]; }
#pragma unroll
        for (int h = 0; h < 2; ++h) {
            int row = row0 + h * 8;
            float v0 = d[nt][2 * h + 0] + b0;
            float v1 = d[nt][2 * h + 1] + b1;
            if (g.relu) { v0 = fmaxf(v0, 0.f); v1 = fmaxf(v1, 0.f); }
            size_t o = (size_t)row * g.ldc + ncol;
            if (Cf) { Cf[o] = v0; Cf[o + 1] = v1; }
            if (Ch) {
                __nv_bfloat16 hv[2], lv[2];
                hv[0] = __float2bfloat16(v0);
                lv[0] = __float2bfloat16(v0 - __bfloat162float(hv[0]));
                hv[1] = __float2bfloat16(v1);
                lv[1] = __float2bfloat16(v1 - __bfloat162float(hv[1]));
                *(uint32_t*)&Ch[o] = *(uint32_t*)hv;
                *(uint32_t*)&Cl[o] = *(uint32_t*)lv;
            }
        }
    }
}

// ---------------------------------------------------------------------------
// masked relational sum: fp32 in, bf16 hi/lo out
// ---------------------------------------------------------------------------
struct MaskArgs {
    const float* coor[4];
    int cbs[4];
    int cns[4];
    const float* relb;
};

__global__ void mask_relsum_kernel(MaskArgs ma) {
    int b = blockIdx.x, k = blockIdx.y;
    __shared__ float cx[NN], cy[NN], rr[NN], cnt[NN];
    __shared__ int   mask[NN][NN];
    int tid = threadIdx.x;
    if (tid < NN) {
        const float* cp = ma.coor[k] + (size_t)b * ma.cbs[k] + tid * ma.cns[k];
        cx[tid] = cp[0];
        cy[tid] = cp[1];
        rr[tid] = g_r[b * NN + tid];
    }
    __syncthreads();
    if (tid < NN * NN) {
        int i = tid / NN, j = tid % NN;
        float dx = cx[i] - cx[j], dy = cy[i] - cy[j];
        float dist = sqrtf(dx * dx + dy * dy);
        mask[i][j] = (i != j) && (dist <= rr[i] + rr[j]);
    }
    __syncthreads();
    if (tid < NN) {
        int c = 0;
        for (int j = 0; j < NN; ++j) c += mask[tid][j];
        cnt[tid] = (float)c;
    }
    __syncthreads();
    int d = tid;
    float rb = ma.relb[k * ND + d];
    size_t base = (size_t)k * SD + (size_t)b * NN * ND;
    float vv[NN];
#pragma unroll
    for (int j = 0; j < NN; ++j) vv[j] = g_v[base + j * ND + d];
#pragma unroll
    for (int i = 0; i < NN; ++i) {
        float acc = g_selfd[base + i * ND + d] + cnt[i] * (g_u[base + i * ND + d] + rb);
#pragma unroll
        for (int j = 0; j < NN; ++j)
            if (mask[i][j]) acc += vv[j];
        __nv_bfloat16 h = __float2bfloat16(acc);
        g_th[base + i * ND + d] = h;
        g_tl[base + i * ND + d] = __float2bfloat16(acc - __bfloat162float(h));
    }
}

// ---------------------------------------------------------------------------
// agg_finish
// ---------------------------------------------------------------------------
__global__ void agg_finish_kernel(const float* __restrict__ aggb,
                                  const float* __restrict__ dw,
                                  const float* __restrict__ db,
                                  float* __restrict__ out,
                                  __nv_bfloat16* __restrict__ Psth,
                                  __nv_bfloat16* __restrict__ Pstl, int it) {
    int row = blockIdx.x, tid = threadIdx.x;
    size_t off = (size_t)row * ND + tid;
    float s = aggb[tid] + g_aggp[off] + g_aggp[SD + off] +
              g_aggp[2 * SD + off] + g_aggp[3 * SD + off];
    __nv_bfloat16 h = __float2bfloat16(s);
    Psth[off] = h;
    Pstl[off] = __float2bfloat16(s - __bfloat162float(h));
    float p0 = s * dw[tid];
    float p1 = s * dw[256 + tid];
    float p2 = s * dw[512 + tid];
    float p3 = s * dw[768 + tid];
#pragma unroll
    for (int o = 16; o > 0; o >>= 1) {
        p0 += __shfl_down_sync(0xffffffffu, p0, o);
        p1 += __shfl_down_sync(0xffffffffu, p1, o);
        p2 += __shfl_down_sync(0xffffffffu, p2, o);
        p3 += __shfl_down_sync(0xffffffffu, p3, o);
    }
    __shared__ float sw[8][4];
    int wid = tid >> 5, lane = tid & 31;
    if (lane == 0) { sw[wid][0] = p0; sw[wid][1] = p1; sw[wid][2] = p2; sw[wid][3] = p3; }
    __syncthreads();
    if (tid < 4) {
        float acc = db[tid];
#pragma unroll
        for (int w = 0; w < 8; ++w) acc += sw[w][tid];
        int b = row / NN, n = row % NN;
        out[(size_t)b * (NROLL * NN * 4) + it * (NN * 4) + n * 4 + tid] = acc;
    }
}

// ---------------------------------------------------------------------------
// Host launchers
// ---------------------------------------------------------------------------
static void launch_gemm(int numZ, int M, int K1, int K2,
                        const float* const* A1, int lda1,
                        const float* const* A2, int lda2,
                        const float* const* W, const int* ldw,
                        const float* const* Bias,
                        float* const* C, int ldc, int relu) {
    GemmArgs ga;
    for (int z = 0; z < numZ; ++z) {
        ga.A1[z] = A1[z];
        ga.A2[z] = A2 ? A2[z] : A1[z];
        ga.W[z] = W[z];
        ga.Bias[z] = Bias ? Bias[z] : nullptr;
        ga.C[z] = C[z];
        ga.ldw[z] = ldw[z];
    }
    for (int z = numZ; z < 12; ++z) {
        ga.A1[z] = ga.A1[0]; ga.A2[z] = ga.A2[0]; ga.W[z] = ga.W[0];
        ga.Bias[z] = nullptr; ga.C[z] = ga.C[0]; ga.ldw[z] = ga.ldw[0];
    }
    ga.lda1 = lda1; ga.lda2 = lda2; ga.ldc = ldc;
    ga.K1 = K1; ga.K2 = K2; ga.relu = relu;
    dim3 grid(M / 64, 4, numZ);
    gemm_nt_kernel<<<grid, 256>>>(ga);
}

struct BfSpec {
    const __nv_bfloat16 *ah1, *al1, *ah2, *al2;
    int whoff;
    const float* bias;
    float* cf;
    __nv_bfloat16 *ch, *cl;
    int ldw;
};

static void launch_gemm_bf(int numZ, const BfSpec* sp,
                           int lda1, int lda2, int ldc, int K1, int K2, int relu) {
    GemmBfArgs ga;
    for (int z = 0; z < numZ; ++z) {
        ga.Ah1[z] = sp[z].ah1; ga.Al1[z] = sp[z].al1;
        ga.Ah2[z] = sp[z].ah2 ? sp[z].ah2 : sp[z].ah1;
        ga.Al2[z] = sp[z].al2 ? sp[z].al2 : sp[z].al1;
        ga.whoff[z] = sp[z].whoff;
        ga.Bias[z] = sp[z].bias;
        ga.Cf[z] = sp[z].cf;
        ga.Ch[z] = sp[z].ch;
        ga.Cl[z] = sp[z].cl;
        ga.ldw[z] = sp[z].ldw;
    }
    for (int z = numZ; z < 12; ++z) {
        ga.Ah1[z] = ga.Ah1[0]; ga.Al1[z] = ga.Al1[0];
        ga.Ah2[z] = ga.Ah2[0]; ga.Al2[z] = ga.Al2[0];
        ga.whoff[z] = ga.whoff[0]; ga.Bias[z] = nullptr;
        ga.Cf[z] = ga.Cf[0]; ga.Ch[z] = ga.Ch[0]; ga.Cl[z] = ga.Cl[0];
        ga.ldw[z] = ga.ldw[0];
    }
    ga.lda1 = lda1; ga.lda2 = lda2; ga.ldc = ldc;
    ga.K1 = K1; ga.K2 = K2; ga.relu = relu;
    dim3 grid(NROW / 64, 4, numZ);
    gemm_bf16_kernel<<<grid, 256>>>(ga);
}

extern "C" void kernel_launch(void* const* d_in, const int* in_sizes, int n_in,
                              void* d_out, int out_size) {
    const float* x       = (const float*)d_in[0];
    const float* rois    = (const float*)d_in[1];
    const float* src     = (const float*)d_in[2];
    const float* w_conv1 = (const float*)d_in[3];
    const float* b_conv1 = (const float*)d_in[4];
    const float* w_conv2 = (const float*)d_in[5];
    const float* b_conv2 = (const float*)d_in[6];
    const float* fc0_w   = (const float*)d_in[7];
    const float* fc0_b   = (const float*)d_in[8];
    const float* fc0c_w  = (const float*)d_in[9];
    const float* fc0c_b  = (const float*)d_in[10];
    const float* fc1c_w  = (const float*)d_in[11];
    const float* fc1c_b  = (const float*)d_in[12];
    const float* red_w   = (const float*)d_in[13];
    const float* red_b   = (const float*)d_in[14];
    const float* g_self_w = (const float*)d_in[15];
    const float* g_self_b = (const float*)d_in[16];
    const float* g_rel_w  = (const float*)d_in[17];
    const float* g_rel_b  = (const float*)d_in[18];
    const float* g_aff_w  = (const float*)d_in[19];
    const float* g_aff_b  = (const float*)d_in[20];
    const float* g_out_w  = (const float*)d_in[21];
    const float* g_out_b  = (const float*)d_in[22];
    const float* agg_w   = (const float*)d_in[23];
    const float* agg_b   = (const float*)d_in[24];
    const float* dec_w   = (const float*)d_in[25];
    const float* dec_b   = (const float*)d_in[26];
    float* outp = (float*)d_out;

    float *pool, *obj, *emb1, *emb2, *sttmp, *selfd, *u, *v, *aggp;
    __nv_bfloat16 *Oh, *Ol, *Ph, *Pl, *th, *tl, *ah, *al, *csh, *csl;
    cudaGetSymbolAddress((void**)&pool,  g_pool);
    cudaGetSymbolAddress((void**)&obj,   g_obj);
    cudaGetSymbolAddress((void**)&emb1,  g_emb1);
    cudaGetSymbolAddress((void**)&emb2,  g_emb2);
    cudaGetSymbolAddress((void**)&sttmp, g_sttmp);
    cudaGetSymbolAddress((void**)&selfd, g_selfd);
    cudaGetSymbolAddress((void**)&u,     g_u);
    cudaGetSymbolAddress((void**)&v,     g_v);
    cudaGetSymbolAddress((void**)&aggp,  g_aggp);
    cudaGetSymbolAddress((void**)&Oh,    g_Oh);
    cudaGetSymbolAddress((void**)&Ol,    g_Ol);
    cudaGetSymbolAddress((void**)&Ph,    g_Ph);
    cudaGetSymbolAddress((void**)&Pl,    g_Pl);
    cudaGetSymbolAddress((void**)&th,    g_th);
    cudaGetSymbolAddress((void**)&tl,    g_tl);
    cudaGetSymbolAddress((void**)&ah,    g_ah);
    cudaGetSymbolAddress((void**)&al,    g_al);
    cudaGetSymbolAddress((void**)&csh,   g_csh);
    cudaGetSymbolAddress((void**)&csl,   g_csl);

    // ---- conversions ----
    cvt2_kernel<<<144, 256>>>(w_conv2);
    cvt1_kernel<<<3, 256>>>(w_conv1);
    xcvt_kernel<<<16384, 256>>>(x);
    {
        CvtArgs ca;
        ca.src[0] = g_self_w; ca.size[0] = 262144; ca.off[0] = OFF_SELF;
        ca.src[1] = g_rel_w;  ca.size[1] = 524288; ca.off[1] = OFF_REL;
        ca.src[2] = g_aff_w;  ca.size[2] = 262144; ca.off[2] = OFF_AFF;
        ca.src[3] = g_out_w;  ca.size[3] = 524288; ca.off[3] = OFF_OUT;
        ca.src[4] = agg_w;    ca.size[4] = 262144; ca.off[4] = OFF_AGG;
        cvt_kernel<<<dim3(512, 5), 256>>>(ca);
    }

    // ---- preamble ----
    r_kernel<<<3, 128>>>(rois);
    conv1_mma_kernel<<<dim3(32, NBT), 256>>>(b_conv1);
    conv2_mma_kernel<<<dim3(8, NBT), 256>>>(b_conv2);
    roi_kernel<<<NROI, 256>>>(rois);
    emb0_kernel<<<NROI, 256>>>(src, fc0c_w, fc0c_b);

    {   // fc1c
        const float* A1[1] = { emb1 };
        const float* W[1] = { fc1c_w }; int ldw[1] = { 256 };
        const float* B[1] = { fc1c_b };
        float* C[1] = { emb2 };
        launch_gemm(1, NROI, 256, 0, A1, 256, nullptr, 0, W, ldw, B, C, ND, 1);
    }
    {   // fc0
        const float* A1[1] = { pool };
        const float* W[1] = { fc0_w }; int ldw[1] = { 1024 };
        const float* B[1] = { fc0_b };
        float* C[1] = { obj };
        launch_gemm(1, NROI, 1024, 0, A1, 1024, nullptr, 0, W, ldw, B, C, ND, 1);
    }
    {   // red
        const float* A1[1] = { obj };
        const float* A2[1] = { emb2 };
        const float* W[1] = { red_w }; int ldw[1] = { 512 };
        const float* B[1] = { red_b };
        float* C[1] = { sttmp };
        launch_gemm(1, NROI, 256, 256, A1, 256, A2, 256, W, ldw, B, C, ND, 1);
    }
    rearr_kernel<<<NROI, 256>>>();

    // ---- rollouts ----
    for (int it = 0; it < NROLL; ++it) {
        const __nv_bfloat16 *sth[4], *stl[4];
        MaskArgs ma;
        for (int k = 0; k < 4; ++k) {
            int idx = it + k;
            if (idx < 4) {
                sth[k] = Oh + (size_t)idx * SD;
                stl[k] = Ol + (size_t)idx * SD;
                ma.coor[k] = src + idx * (NN * 2);
                ma.cbs[k] = NT * NN * 2;
                ma.cns[k] = 2;
            } else {
                sth[k] = Ph + (size_t)(idx - 4) * SD;
                stl[k] = Pl + (size_t)(idx - 4) * SD;
                ma.coor[k] = outp + (idx - 4) * (NN * 4) + 2;
                ma.cbs[k] = NROLL * NN * 4;
                ma.cns[k] = 4;
            }
        }
        ma.relb = g_rel_b;

        {   // selfd / u / v
            BfSpec sp[12];
            for (int z = 0; z < 12; ++z) {
                int k = z & 3, kind = z >> 2;
                sp[z].ah1 = sth[k]; sp[z].al1 = stl[k];
                sp[z].ah2 = nullptr; sp[z].al2 = nullptr;
                sp[z].ch = nullptr; sp[z].cl = nullptr;
                if (kind == 0)      { sp[z].whoff = OFF_SELF + k * 65536;       sp[z].ldw = 256; sp[z].bias = g_self_b + k * 256; sp[z].cf = selfd + (size_t)k * SD; }
                else if (kind == 1) { sp[z].whoff = OFF_REL + k * 131072;       sp[z].ldw = 512; sp[z].bias = nullptr;            sp[z].cf = u + (size_t)k * SD; }
                else                { sp[z].whoff = OFF_REL + k * 131072 + 256; sp[z].ldw = 512; sp[z].bias = nullptr;            sp[z].cf = v + (size_t)k * SD; }
            }
            launch_gemm_bf(12, sp, 256, 256, ND, 256, 0, 0);
        }
        mask_relsum_kernel<<<dim3(NB, 4), 256>>>(ma);
        {   // aff
            BfSpec sp[4];
            for (int k = 0; k < 4; ++k) {
                sp[k].ah1 = th + (size_t)k * SD; sp[k].al1 = tl + (size_t)k * SD;
                sp[k].ah2 = nullptr; sp[k].al2 = nullptr;
                sp[k].whoff = OFF_AFF + k * 65536; sp[k].ldw = 256;
                sp[k].bias = g_aff_b + k * 256;
                sp[k].cf = nullptr;
                sp[k].ch = ah + (size_t)k * SD; sp[k].cl = al + (size_t)k * SD;
            }
            launch_gemm_bf(4, sp, 256, 256, ND, 256, 0, 1);
        }
        {   // out
            BfSpec sp[4];
            for (int k = 0; k < 4; ++k) {
                sp[k].ah1 = ah + (size_t)k * SD; sp[k].al1 = al + (size_t)k * SD;
                sp[k].ah2 = sth[k]; sp[k].al2 = stl[k];
                sp[k].whoff = OFF_OUT + k * 131072; sp[k].ldw = 512;
                sp[k].bias = g_out_b + k * 256;
                sp[k].cf = nullptr;
                sp[k].ch = csh + k * 256; sp[k].cl = csl + k * 256;
            }
            launch_gemm_bf(4, sp, 256, 256, 1024, 256, 256, 1);
        }
        {   // agg split-K x4
            BfSpec sp[4];
            for (int z = 0; z < 4; ++z) {
                sp[z].ah1 = csh + z * 256; sp[z].al1 = csl + z * 256;
                sp[z].ah2 = nullptr; sp[z].al2 = nullptr;
                sp[z].whoff = OFF_AGG + z * 256; sp[z].ldw = 1024;
                sp[z].bias = nullptr;
                sp[z].cf = aggp + (size_t)z * SD;
                sp[z].ch = nullptr; sp[z].cl = nullptr;
            }
            launch_gemm_bf(4, sp, 1024, 1024, ND, 256, 0, 0);
        }
        agg_finish_kernel<<<NROW, 256>>>(agg_b, dec_w, dec_b, outp,
                                         Ph + (size_t)it * SD, Pl + (size_t)it * SD, it);
    }

    (void)in_sizes; (void)n_in; (void)out_size;
}

// round 17
// speedup vs baseline: 1.5240x; 1.0112x over previous
#include <cuda_runtime.h>
#include <cuda_bf16.h>
#include <cstdint>

// ---------------------------------------------------------------------------
// Problem constants: B=64, T=4, N=6, IMG=128, CIN=3, VE=64, D=256, P=4, R=8
// ---------------------------------------------------------------------------
#define NB 64
#define NT 4
#define NN 6
#define NBT 256            // B*T
#define NROI 1536          // B*T*N
#define NROW 384           // B*N
#define ND 256
#define SD (NROW*ND)
#define NROLL 8

// ---------------------------------------------------------------------------
// Device scratch
// ---------------------------------------------------------------------------
__device__ __nv_bfloat16 g_x4h[(size_t)NBT * 128 * 128 * 4];
__device__ __nv_bfloat16 g_x4l[(size_t)NBT * 128 * 128 * 4];
__device__ __nv_bfloat16 g_w1h[9 * 64 * 4];
__device__ __nv_bfloat16 g_w1l[9 * 64 * 4];
__device__ __nv_bfloat16 g_f1h[(size_t)NBT * 64 * 64 * 64];   // channel-last
__device__ __nv_bfloat16 g_f1l[(size_t)NBT * 64 * 64 * 64];
__device__ __nv_bfloat16 g_w2h[9 * 64 * 64];
__device__ __nv_bfloat16 g_w2l[9 * 64 * 64];
__device__ float g_f2[(size_t)NBT * 64 * 32 * 32];
__device__ float g_pool [NROI * 1024];
__device__ float g_obj  [NROI * ND];
__device__ float g_emb1 [NROI * ND];
__device__ float g_emb2 [NROI * ND];
__device__ float g_sttmp[NROI * ND];
__device__ float g_selfd[4 * SD];
__device__ float g_u[4 * SD];
__device__ float g_v[4 * SD];
__device__ float g_aggp[4 * SD];
__device__ float g_r[NROW];
__device__ __nv_bfloat16 g_Oh[4 * SD],  g_Ol[4 * SD];
__device__ __nv_bfloat16 g_Ph[8 * SD],  g_Pl[8 * SD];
__device__ __nv_bfloat16 g_th[4 * SD],  g_tl[4 * SD];
__device__ __nv_bfloat16 g_ah[4 * SD],  g_al[4 * SD];
__device__ __nv_bfloat16 g_csh[NROW * 1024], g_csl[NROW * 1024];
#define OFF_SELF 0
#define OFF_REL  262144
#define OFF_AFF  786432
#define OFF_OUT  1048576
#define OFF_AGG  1572864
#define WTOTAL   1835008
__device__ __nv_bfloat16 g_wh[WTOTAL];
__device__ __nv_bfloat16 g_wl[WTOTAL];

// ---------------------------------------------------------------------------
// conversions
// ---------------------------------------------------------------------------
__global__ void cvt2_kernel(const float* __restrict__ w2) {
    int i = blockIdx.x * 256 + threadIdx.x;
    if (i >= 9 * 64 * 64) return;
    int ci = i & 63, n = (i >> 6) & 63, tap = i >> 12;
    float v = w2[(size_t)n * 576 + ci * 9 + tap];
    __nv_bfloat16 h = __float2bfloat16(v);
    g_w2h[i] = h;
    g_w2l[i] = __float2bfloat16(v - __bfloat162float(h));
}

__global__ void cvt1_kernel(const float* __restrict__ w1) {
    int i = blockIdx.x * 256 + threadIdx.x;
    if (i >= 576) return;
    int co = i % 64, tap = i / 64;
    __nv_bfloat16 hv[4], lv[4];
#pragma unroll
    for (int ci = 0; ci < 3; ++ci) {
        float v = w1[(size_t)co * 27 + ci * 9 + tap];
        hv[ci] = __float2bfloat16(v);
        lv[ci] = __float2bfloat16(v - __bfloat162float(hv[ci]));
    }
    hv[3] = __float2bfloat16(0.f);
    lv[3] = __float2bfloat16(0.f);
    *(uint2*)&g_w1h[(size_t)i * 4] = *(uint2*)hv;
    *(uint2*)&g_w1l[(size_t)i * 4] = *(uint2*)lv;
}

__global__ void xcvt_kernel(const float* __restrict__ x) {
    size_t p = (size_t)blockIdx.x * 256 + threadIdx.x;
    size_t bt = p >> 14, px = p & 16383;
    const float* xp = x + bt * 3 * 16384 + px;
    __nv_bfloat16 hv[4], lv[4];
#pragma unroll
    for (int ci = 0; ci < 3; ++ci) {
        float v = xp[(size_t)ci * 16384];
        hv[ci] = __float2bfloat16(v);
        lv[ci] = __float2bfloat16(v - __bfloat162float(hv[ci]));
    }
    hv[3] = __float2bfloat16(0.f);
    lv[3] = __float2bfloat16(0.f);
    *(uint2*)&g_x4h[p * 4] = *(uint2*)hv;
    *(uint2*)&g_x4l[p * 4] = *(uint2*)lv;
}

// vectorized: 4 elements per thread
struct CvtArgs { const float* src[5]; int size[5]; int off[5]; };
__global__ void cvt_kernel(CvtArgs c) {
    int seg = blockIdx.y;
    int i4 = (blockIdx.x * 256 + threadIdx.x) * 4;
    if (i4 >= c.size[seg]) return;
    float4 v = *(const float4*)(c.src[seg] + i4);
    __nv_bfloat16 hv[4], lv[4];
    hv[0] = __float2bfloat16(v.x); lv[0] = __float2bfloat16(v.x - __bfloat162float(hv[0]));
    hv[1] = __float2bfloat16(v.y); lv[1] = __float2bfloat16(v.y - __bfloat162float(hv[1]));
    hv[2] = __float2bfloat16(v.z); lv[2] = __float2bfloat16(v.z - __bfloat162float(hv[2]));
    hv[3] = __float2bfloat16(v.w); lv[3] = __float2bfloat16(v.w - __bfloat162float(hv[3]));
    *(uint2*)&g_wh[c.off[seg] + i4] = *(uint2*)hv;
    *(uint2*)&g_wl[c.off[seg] + i4] = *(uint2*)lv;
}

// ---------------------------------------------------------------------------
__global__ void r_kernel(const float* __restrict__ rois) {
    int i = blockIdx.x * 128 + threadIdx.x;
    if (i >= NROW) return;
    int b = i / NN, n = i % NN;
    float s = 0.f;
    for (int t = 0; t < NT; ++t) {
        const float* ro = rois + (size_t)(((b * NT + t) * NN) + n) * 5;
        s += ((ro[4] - ro[2]) * 0.5f + (ro[3] - ro[1]) * 0.5f) * 0.5f;
    }
    g_r[i] = s * 0.25f;
}

// ---------------------------------------------------------------------------
#define MMA_BF16(d, a0, a1, a2, a3, b0, b1)                                    \
    asm volatile(                                                              \
        "mma.sync.aligned.m16n8k16.row.col.f32.bf16.bf16.f32 "                \
        "{%0,%1,%2,%3},{%4,%5,%6,%7},{%8,%9},{%0,%1,%2,%3};"                  \
        : "+f"(d[0]), "+f"(d[1]), "+f"(d[2]), "+f"(d[3])                       \
        : "r"(a0), "r"(a1), "r"(a2), "r"(a3), "r"(b0), "r"(b1))

// ---------------------------------------------------------------------------
// conv1 via tensor cores (proven round 11)
// ---------------------------------------------------------------------------
__global__ void conv1_mma_kernel(const float* __restrict__ b1) {
    __shared__ __nv_bfloat16 Ah[128 * 56];
    __shared__ __nv_bfloat16 Al[128 * 56];
    __shared__ __nv_bfloat16 Bh[64 * 56];
    __shared__ __nv_bfloat16 Bl[64 * 56];

    int tid = threadIdx.x;
    int w = tid >> 5, lane = tid & 31;
    int g = lane >> 2, tq = lane & 3;
    int bx = blockIdx.x, bt = blockIdx.y;
    int oy0 = bx * 2;
    const __nv_bfloat16* xh = g_x4h + (size_t)bt * 16384 * 4;
    const __nv_bfloat16* xl = g_x4l + (size_t)bt * 16384 * 4;

    {
        uint4 z = make_uint4(0u, 0u, 0u, 0u);
        uint4* a4h = (uint4*)Ah; uint4* a4l = (uint4*)Al;
        for (int i = tid; i < 896; i += 256) { a4h[i] = z; a4l[i] = z; }
        uint4* b4h = (uint4*)Bh; uint4* b4l = (uint4*)Bl;
        for (int i = tid; i < 448; i += 256) { b4h[i] = z; b4l[i] = z; }
    }
    __syncthreads();

    for (int idx = tid; idx < 1152; idx += 256) {
        int t9 = idx >> 7, m = idx & 127;
        int kh = t9 / 3, kw = t9 - 3 * kh;
        int dy = m >> 6, ox = m & 63;
        int iy = 2 * (oy0 + dy) + kh;
        int ix = 2 * ox + kw;
        if (iy < 128 && ix < 128) {
            size_t src = ((size_t)iy * 128 + ix) * 4;
            *(uint2*)&Ah[m * 56 + t9 * 4] = *(const uint2*)&xh[src];
            *(uint2*)&Al[m * 56 + t9 * 4] = *(const uint2*)&xl[src];
        }
    }
    for (int idx = tid; idx < 576; idx += 256) {
        int t9 = idx / 64, co = idx % 64;
        *(uint2*)&Bh[co * 56 + t9 * 4] = *(const uint2*)&g_w1h[(size_t)idx * 4];
        *(uint2*)&Bl[co * 56 + t9 * 4] = *(const uint2*)&g_w1l[(size_t)idx * 4];
    }
    __syncthreads();

    float d[8][4] = {};
#pragma unroll
    for (int ks = 0; ks < 3; ++ks) {
        int k0 = ks * 16 + tq * 2;
        int r0 = w * 16 + g;
        uint32_t ah0 = *(const uint32_t*)&Ah[r0 * 56 + k0];
        uint32_t ah1 = *(const uint32_t*)&Ah[(r0 + 8) * 56 + k0];
        uint32_t ah2 = *(const uint32_t*)&Ah[r0 * 56 + k0 + 8];
        uint32_t ah3 = *(const uint32_t*)&Ah[(r0 + 8) * 56 + k0 + 8];
        uint32_t al0 = *(const uint32_t*)&Al[r0 * 56 + k0];
        uint32_t al1 = *(const uint32_t*)&Al[(r0 + 8) * 56 + k0];
        uint32_t al2 = *(const uint32_t*)&Al[r0 * 56 + k0 + 8];
        uint32_t al3 = *(const uint32_t*)&Al[(r0 + 8) * 56 + k0 + 8];
#pragma unroll
        for (int nt = 0; nt < 8; ++nt) {
            int nr = nt * 8 + g;
            uint32_t bh0 = *(const uint32_t*)&Bh[nr * 56 + k0];
            uint32_t bh1 = *(const uint32_t*)&Bh[nr * 56 + k0 + 8];
            uint32_t bl0 = *(const uint32_t*)&Bl[nr * 56 + k0];
            uint32_t bl1 = *(const uint32_t*)&Bl[nr * 56 + k0 + 8];
            MMA_BF16(d[nt], ah0, ah1, ah2, ah3, bh0, bh1);
            MMA_BF16(d[nt], ah0, ah1, ah2, ah3, bl0, bl1);
            MMA_BF16(d[nt], al0, al1, al2, al3, bh0, bh1);
        }
    }

#pragma unroll
    for (int nt = 0; nt < 8; ++nt) {
        int co = nt * 8 + tq * 2;
        int px = w * 16 + g;
        float bias0 = b1[co], bias1 = b1[co + 1];
#pragma unroll
        for (int h = 0; h < 2; ++h) {
            int m = px + h * 8;
            int dy = m >> 6, ox = m & 63;
            float v0 = fmaxf(d[nt][2 * h + 0] + bias0, 0.f);
            float v1 = fmaxf(d[nt][2 * h + 1] + bias1, 0.f);
            __nv_bfloat16 hv[2], lv[2];
            hv[0] = __float2bfloat16(v0);
            lv[0] = __float2bfloat16(v0 - __bfloat162float(hv[0]));
            hv[1] = __float2bfloat16(v1);
            lv[1] = __float2bfloat16(v1 - __bfloat162float(hv[1]));
            size_t o = (((size_t)bt * 4096) + (oy0 + dy) * 64 + ox) * 64 + co;
            *(uint32_t*)&g_f1h[o] = *(uint32_t*)hv;
            *(uint32_t*)&g_f1l[o] = *(uint32_t*)lv;
        }
    }
}

// ---------------------------------------------------------------------------
// conv2 via tensor cores, SOFTWARE-PIPELINED, macro-based (no lambdas):
// double-buffered dynamic smem + explicit uint4 register prefetch, 1 sync/rnd.
// ---------------------------------------------------------------------------
#define C2_A 5120              // 128*40 per plane per buffer
#define C2_B 2560              // 64*40
#define C2_BUF (2*C2_A + 2*C2_B)   // 15360 elems per buffer
#define CONV2_SMEM (2 * C2_BUF * 2)  // 61440 bytes

#define C2_LOAD(s) do {                                                        \
    int tap_ = (s) >> 1, half_ = (s) & 1;                                      \
    int kh_ = tap_ / 3, kw_ = tap_ - 3 * kh_;                                  \
    int cb_ = half_ * 32;                                                      \
    {                                                                          \
        int dy_ = am0 >> 5, ox_ = am0 & 31;                                    \
        int iy_ = 2 * (bx * 4 + dy_) + kh_;                                    \
        int ix_ = 2 * ox_ + kw_;                                               \
        if (iy_ < 64 && ix_ < 64) {                                            \
            size_t src_ = ((size_t)iy_ * 64 + ix_) * 64 + cb_ + ac * 8;        \
            ra0h = *(const uint4*)&f1h[src_];                                  \
            ra0l = *(const uint4*)&f1l[src_];                                  \
        } else { ra0h = zero4; ra0l = zero4; }                                 \
    }                                                                          \
    {                                                                          \
        int dy_ = am1 >> 5, ox_ = am1 & 31;                                    \
        int iy_ = 2 * (bx * 4 + dy_) + kh_;                                    \
        int ix_ = 2 * ox_ + kw_;                                               \
        if (iy_ < 64 && ix_ < 64) {                                            \
            size_t src_ = ((size_t)iy_ * 64 + ix_) * 64 + cb_ + ac * 8;        \
            ra1h = *(const uint4*)&f1h[src_];                                  \
            ra1l = *(const uint4*)&f1l[src_];                                  \
        } else { ra1h = zero4; ra1l = zero4; }                                 \
    }                                                                          \
    {                                                                          \
        int src_ = tap_ * 4096 + bn * 64 + cb_ + bc * 8;                       \
        rbh = *(const uint4*)&g_w2h[src_];                                     \
        rbl = *(const uint4*)&g_w2l[src_];                                     \
    }                                                                          \
} while (0)

#define C2_STORE(q) do {                                                       \
    __nv_bfloat16* Ah_ = smraw + (size_t)(q) * C2_BUF;                         \
    __nv_bfloat16* Al_ = Ah_ + C2_A;                                           \
    __nv_bfloat16* Bh_ = Al_ + C2_A;                                           \
    __nv_bfloat16* Bl_ = Bh_ + C2_B;                                           \
    *(uint4*)&Ah_[am0 * 40 + ac * 8] = ra0h;                                   \
    *(uint4*)&Al_[am0 * 40 + ac * 8] = ra0l;                                   \
    *(uint4*)&Ah_[am1 * 40 + ac * 8] = ra1h;                                   \
    *(uint4*)&Al_[am1 * 40 + ac * 8] = ra1l;                                   \
    *(uint4*)&Bh_[bn * 40 + bc * 8] = rbh;                                     \
    *(uint4*)&Bl_[bn * 40 + bc * 8] = rbl;                                     \
} while (0)

__global__ void __launch_bounds__(256, 2)
conv2_mma_kernel(const float* __restrict__ b2) {
    extern __shared__ __nv_bfloat16 smraw[];
    int tid = threadIdx.x;
    int w = tid >> 5, lane = tid & 31;
    int g = lane >> 2, tq = lane & 3;
    int bx = blockIdx.x, bt = blockIdx.y;
    const __nv_bfloat16* f1h = g_f1h + (size_t)bt * 4096 * 64;
    const __nv_bfloat16* f1l = g_f1l + (size_t)bt * 4096 * 64;

    const int am0 = tid >> 2, ac = tid & 3;
    const int am1 = am0 + 64;
    const int bn = tid >> 2, bc = tid & 3;
    const uint4 zero4 = make_uint4(0u, 0u, 0u, 0u);

    uint4 ra0h, ra0l, ra1h, ra1l, rbh, rbl;
    float d[8][4] = {};

    C2_LOAD(0);
    C2_STORE(0);
    C2_LOAD(1);
    __syncthreads();

    int p = 0;
#pragma unroll 1
    for (int s = 0; s < 18; ++s) {
        if (s + 1 < 18) C2_STORE(p ^ 1);
        if (s + 2 < 18) C2_LOAD(s + 2);

        const __nv_bfloat16* Ah = smraw + (size_t)p * C2_BUF;
        const __nv_bfloat16* Al = Ah + C2_A;
        const __nv_bfloat16* Bh = Al + C2_A;
        const __nv_bfloat16* Bl = Bh + C2_B;
#pragma unroll
        for (int ks = 0; ks < 2; ++ks) {
            int k0 = ks * 16 + tq * 2;
            int r0 = w * 16 + g;
            uint32_t ah0 = *(const uint32_t*)&Ah[r0 * 40 + k0];
            uint32_t ah1 = *(const uint32_t*)&Ah[(r0 + 8) * 40 + k0];
            uint32_t ah2 = *(const uint32_t*)&Ah[r0 * 40 + k0 + 8];
            uint32_t ah3 = *(const uint32_t*)&Ah[(r0 + 8) * 40 + k0 + 8];
            uint32_t al0 = *(const uint32_t*)&Al[r0 * 40 + k0];
            uint32_t al1 = *(const uint32_t*)&Al[(r0 + 8) * 40 + k0];
            uint32_t al2 = *(const uint32_t*)&Al[r0 * 40 + k0 + 8];
            uint32_t al3 = *(const uint32_t*)&Al[(r0 + 8) * 40 + k0 + 8];
#pragma unroll
            for (int nt = 0; nt < 8; ++nt) {
                int nr = nt * 8 + g;
                uint32_t bh0 = *(const uint32_t*)&Bh[nr * 40 + k0];
                uint32_t bh1 = *(const uint32_t*)&Bh[nr * 40 + k0 + 8];
                uint32_t bl0 = *(const uint32_t*)&Bl[nr * 40 + k0];
                uint32_t bl1 = *(const uint32_t*)&Bl[nr * 40 + k0 + 8];
                MMA_BF16(d[nt], ah0, ah1, ah2, ah3, bh0, bh1);
                MMA_BF16(d[nt], ah0, ah1, ah2, ah3, bl0, bl1);
                MMA_BF16(d[nt], al0, al1, al2, al3, bh0, bh1);
            }
        }
        if (s + 1 < 18) __syncthreads();
        p ^= 1;
    }

    int oyb = bx * 4;
#pragma unroll
    for (int nt = 0; nt < 8; ++nt) {
        int co = nt * 8 + tq * 2;
        int px = w * 16 + g;
        float bias0 = b2[co], bias1 = b2[co + 1];
#pragma unroll
        for (int h = 0; h < 2; ++h) {
            int p2 = px + h * 8;
            int dy = p2 >> 5, ox = p2 & 31;
            size_t base = (((size_t)bt * 64 + co) * 32 + oyb + dy) * 32 + ox;
            g_f2[base]        = fmaxf(d[nt][2 * h + 0] + bias0, 0.f);
            g_f2[base + 1024] = fmaxf(d[nt][2 * h + 1] + bias1, 0.f);
        }
    }
}

// ---------------------------------------------------------------------------
__global__ void roi_kernel(const float* __restrict__ rois) {
    int r = blockIdx.x;
    __shared__ float ro[5];
    if (threadIdx.x < 5) ro[threadIdx.x] = rois[(size_t)r * 5 + threadIdx.x];
    __syncthreads();
    int bt = (int)ro[0];
    float x1 = ro[1] * 0.25f, y1 = ro[2] * 0.25f;
    float x2 = ro[3] * 0.25f, y2 = ro[4] * 0.25f;
    float bw = fmaxf(x2 - x1, 1.f) * 0.25f;
    float bh = fmaxf(y2 - y1, 1.f) * 0.25f;
    for (int idx = threadIdx.x; idx < 1024; idx += 256) {
        int c = idx >> 4, py = (idx >> 2) & 3, px = idx & 3;
        float sx = x1 + bw * (px + 0.5f);
        float sy = y1 + bh * (py + 0.5f);
        float x0f = fminf(fmaxf(floorf(sx), 0.f), 31.f);
        float y0f = fminf(fmaxf(floorf(sy), 0.f), 31.f);
        float lx = fminf(fmaxf(sx - x0f, 0.f), 1.f);
        float ly = fminf(fmaxf(sy - y0f, 0.f), 1.f);
        int x0 = (int)x0f, y0 = (int)y0f;
        int x1i = min(x0 + 1, 31), y1i = min(y0 + 1, 31);
        const float* f = &g_f2[((size_t)bt * 64 + c) * 1024];
        float v00 = f[y0 * 32 + x0];
        float v01 = f[y0 * 32 + x1i];
        float v10 = f[y1i * 32 + x0];
        float v11 = f[y1i * 32 + x1i];
        float val = v00 * (1.f - ly) * (1.f - lx) + v01 * (1.f - ly) * lx +
                    v10 * ly * (1.f - lx) + v11 * ly * lx;
        g_pool[(size_t)r * 1024 + idx] = val;
    }
}

// ---------------------------------------------------------------------------
__global__ void emb0_kernel(const float* __restrict__ sc,
                            const float* __restrict__ w,
                            const float* __restrict__ b) {
    int row = blockIdx.x, c = threadIdx.x;
    float x0 = sc[(size_t)row * 2], x1 = sc[(size_t)row * 2 + 1];
    float e = fmaf(w[c * 2], x0, fmaf(w[c * 2 + 1], x1, b[c]));
    g_emb1[(size_t)row * ND + c] = fmaxf(e, 0.f);
}

__global__ void rearr_kernel() {
    int i = blockIdx.x * 256 + threadIdx.x;
    int d = i & 255;
    int m = i >> 8;
    int n = m % NN;
    int t = (m / NN) % NT;
    int b = m / (NN * NT);
    float v = g_sttmp[i];
    __nv_bfloat16 h = __float2bfloat16(v);
    size_t o = ((size_t)t * NROW + b * NN + n) * ND + d;
    g_Oh[o] = h;
    g_Ol[o] = __float2bfloat16(v - __bfloat162float(h));
}

// ---------------------------------------------------------------------------
// Scalar pipelined NT GEMM (round 8, preamble only)
// ---------------------------------------------------------------------------
struct GemmArgs {
    const float* A1[12];
    const float* A2[12];
    const float* W[12];
    const float* Bias[12];
    float*       C[12];
    int          ldw[12];
    int lda1, lda2, ldc, K1, K2, relu;
};

__global__ void gemm_nt_kernel(GemmArgs g) {
    const int z = blockIdx.z;
    const float* __restrict__ A1 = g.A1[z];
    const float* __restrict__ A2 = g.A2[z];
    const float* __restrict__ W  = g.W[z];
    const float* __restrict__ Bv = g.Bias[z];
    float* __restrict__ C = g.C[z];
    const int ldw = g.ldw[z];
    const int m0 = blockIdx.x * 64, n0 = blockIdx.y * 64;
    __shared__ float As[2][16 * 68];
    __shared__ float Ws[2][16 * 68];
    const int tid = threadIdx.x;
    const int lr = tid >> 2, lc = (tid & 3) * 4;
    const int ty = tid >> 4, tx = tid & 15;
    float acc[4][4] = {};
    const int K = g.K1 + g.K2;
    const int niter = K >> 4;
    const float* wrow = W + (size_t)(n0 + lr) * ldw;

    float4 av, wv;
    {
        int col = lc;
        const float* ap = (col < g.K1)
            ? A1 + (size_t)(m0 + lr) * g.lda1 + col
            : A2 + (size_t)(m0 + lr) * g.lda2 + (col - g.K1);
        av = *(const float4*)ap;
        wv = *(const float4*)(wrow + col);
    }
    As[0][(lc + 0) * 68 + lr] = av.x; As[0][(lc + 1) * 68 + lr] = av.y;
    As[0][(lc + 2) * 68 + lr] = av.z; As[0][(lc + 3) * 68 + lr] = av.w;
    Ws[0][(lc + 0) * 68 + lr] = wv.x; Ws[0][(lc + 1) * 68 + lr] = wv.y;
    Ws[0][(lc + 2) * 68 + lr] = wv.z; Ws[0][(lc + 3) * 68 + lr] = wv.w;
    if (niter > 1) {
        int col = 16 + lc;
        const float* ap = (col < g.K1)
            ? A1 + (size_t)(m0 + lr) * g.lda1 + col
            : A2 + (size_t)(m0 + lr) * g.lda2 + (col - g.K1);
        av = *(const float4*)ap;
        wv = *(const float4*)(wrow + col);
    }
    __syncthreads();

    int p = 0;
#pragma unroll 1
    for (int i = 0; i < niter; ++i) {
        if (i + 1 < niter) {
            int q = p ^ 1;
            As[q][(lc + 0) * 68 + lr] = av.x; As[q][(lc + 1) * 68 + lr] = av.y;
            As[q][(lc + 2) * 68 + lr] = av.z; As[q][(lc + 3) * 68 + lr] = av.w;
            Ws[q][(lc + 0) * 68 + lr] = wv.x; Ws[q][(lc + 1) * 68 + lr] = wv.y;
            Ws[q][(lc + 2) * 68 + lr] = wv.z; Ws[q][(lc + 3) * 68 + lr] = wv.w;
        }
        if (i + 2 < niter) {
            int col = (i + 2) * 16 + lc;
            const float* ap = (col < g.K1)
                ? A1 + (size_t)(m0 + lr) * g.lda1 + col
                : A2 + (size_t)(m0 + lr) * g.lda2 + (col - g.K1);
            av = *(const float4*)ap;
            wv = *(const float4*)(wrow + col);
        }
#pragma unroll
        for (int k = 0; k < 16; ++k) {
            float4 a = *(const float4*)&As[p][k * 68 + ty * 4];
            float4 b = *(const float4*)&Ws[p][k * 68 + tx * 4];
            acc[0][0] += a.x * b.x; acc[0][1] += a.x * b.y; acc[0][2] += a.x * b.z; acc[0][3] += a.x * b.w;
            acc[1][0] += a.y * b.x; acc[1][1] += a.y * b.y; acc[1][2] += a.y * b.z; acc[1][3] += a.y * b.w;
            acc[2][0] += a.z * b.x; acc[2][1] += a.z * b.y; acc[2][2] += a.z * b.z; acc[2][3] += a.z * b.w;
            acc[3][0] += a.w * b.x; acc[3][1] += a.w * b.y; acc[3][2] += a.w * b.z; acc[3][3] += a.w * b.w;
        }
        if (i + 1 < niter) __syncthreads();
        p ^= 1;
    }

    int n = n0 + tx * 4;
    float b0 = 0.f, b1 = 0.f, b2 = 0.f, b3 = 0.f;
    if (Bv) { b0 = Bv[n]; b1 = Bv[n + 1]; b2 = Bv[n + 2]; b3 = Bv[n + 3]; }
#pragma unroll
    for (int i = 0; i < 4; ++i) {
        float4 o;
        o.x = acc[i][0] + b0; o.y = acc[i][1] + b1;
        o.z = acc[i][2] + b2; o.w = acc[i][3] + b3;
        if (g.relu) {
            o.x = fmaxf(o.x, 0.f); o.y = fmaxf(o.y, 0.f);
            o.z = fmaxf(o.z, 0.f); o.w = fmaxf(o.w, 0.f);
        }
        *(float4*)(C + (size_t)(m0 + ty * 4 + i) * g.ldc + n) = o;
    }
}

// ---------------------------------------------------------------------------
// Tensor-core GEMM for rollout, SOFTWARE-PIPELINED (proven round 14)
// ---------------------------------------------------------------------------
struct GemmBfArgs {
    const __nv_bfloat16* Ah1[12];
    const __nv_bfloat16* Al1[12];
    const __nv_bfloat16* Ah2[12];
    const __nv_bfloat16* Al2[12];
    int whoff[12];
    const float* Bias[12];
    float* Cf[12];
    __nv_bfloat16* Ch[12];
    __nv_bfloat16* Cl[12];
    int ldw[12];
    int lda1, lda2, ldc, K1, K2, relu;
};

__global__ void gemm_bf16_kernel(GemmBfArgs g) {
    const int z = blockIdx.z;
    const __nv_bfloat16* __restrict__ A1h = g.Ah1[z];
    const __nv_bfloat16* __restrict__ A1l = g.Al1[z];
    const __nv_bfloat16* __restrict__ A2h = g.Ah2[z];
    const __nv_bfloat16* __restrict__ A2l = g.Al2[z];
    const __nv_bfloat16* __restrict__ Wh = g_wh + g.whoff[z];
    const __nv_bfloat16* __restrict__ Wl = g_wl + g.whoff[z];
    const float* __restrict__ Bv = g.Bias[z];
    float* __restrict__ Cf = g.Cf[z];
    __nv_bfloat16* __restrict__ Ch = g.Ch[z];
    __nv_bfloat16* __restrict__ Cl = g.Cl[z];
    const int ldw = g.ldw[z];
    const int m0 = blockIdx.x * 64, n0 = blockIdx.y * 64;

    __shared__ __nv_bfloat16 Ahs[2][64 * 40];
    __shared__ __nv_bfloat16 Als[2][64 * 40];
    __shared__ __nv_bfloat16 Bhs[2][64 * 40];
    __shared__ __nv_bfloat16 Bls[2][64 * 40];

    const int tid = threadIdx.x;
    const int wid = tid >> 5, lane = tid & 31;
    const int gq = lane >> 2, tq = lane & 3;
    const int wm = wid >> 1, wn = wid & 1;
    const int sm = tid >> 2, sc = tid & 3;

    float d[4][4] = {};
    const int K = g.K1 + g.K2;
    const int niter = K >> 5;

    uint4 rah, ral, rbh, rbl;

    {
        int col = sc * 8;
        const __nv_bfloat16 *ah, *al;
        if (col < g.K1) {
            ah = A1h + (size_t)(m0 + sm) * g.lda1 + col;
            al = A1l + (size_t)(m0 + sm) * g.lda1 + col;
        } else {
            ah = A2h + (size_t)(m0 + sm) * g.lda2 + (col - g.K1);
            al = A2l + (size_t)(m0 + sm) * g.lda2 + (col - g.K1);
        }
        rah = *(const uint4*)ah;
        ral = *(const uint4*)al;
        size_t src = (size_t)(n0 + sm) * ldw + col;
        rbh = *(const uint4*)&Wh[src];
        rbl = *(const uint4*)&Wl[src];
    }
    *(uint4*)&Ahs[0][sm * 40 + sc * 8] = rah;
    *(uint4*)&Als[0][sm * 40 + sc * 8] = ral;
    *(uint4*)&Bhs[0][sm * 40 + sc * 8] = rbh;
    *(uint4*)&Bls[0][sm * 40 + sc * 8] = rbl;
    if (niter > 1) {
        int col = 32 + sc * 8;
        const __nv_bfloat16 *ah, *al;
        if (col < g.K1) {
            ah = A1h + (size_t)(m0 + sm) * g.lda1 + col;
            al = A1l + (size_t)(m0 + sm) * g.lda1 + col;
        } else {
            ah = A2h + (size_t)(m0 + sm) * g.lda2 + (col - g.K1);
            al = A2l + (size_t)(m0 + sm) * g.lda2 + (col - g.K1);
        }
        rah = *(const uint4*)ah;
        ral = *(const uint4*)al;
        size_t src = (size_t)(n0 + sm) * ldw + col;
        rbh = *(const uint4*)&Wh[src];
        rbl = *(const uint4*)&Wl[src];
    }
    __syncthreads();

    int p = 0;
#pragma unroll 1
    for (int i = 0; i < niter; ++i) {
        if (i + 1 < niter) {
            int q = p ^ 1;
            *(uint4*)&Ahs[q][sm * 40 + sc * 8] = rah;
            *(uint4*)&Als[q][sm * 40 + sc * 8] = ral;
            *(uint4*)&Bhs[q][sm * 40 + sc * 8] = rbh;
            *(uint4*)&Bls[q][sm * 40 + sc * 8] = rbl;
        }
        if (i + 2 < niter) {
            int col = (i + 2) * 32 + sc * 8;
            const __nv_bfloat16 *ah, *al;
            if (col < g.K1) {
                ah = A1h + (size_t)(m0 + sm) * g.lda1 + col;
                al = A1l + (size_t)(m0 + sm) * g.lda1 + col;
            } else {
                ah = A2h + (size_t)(m0 + sm) * g.lda2 + (col - g.K1);
                al = A2l + (size_t)(m0 + sm) * g.lda2 + (col - g.K1);
            }
            rah = *(const uint4*)ah;
            ral = *(const uint4*)al;
            size_t src = (size_t)(n0 + sm) * ldw + col;
            rbh = *(const uint4*)&Wh[src];
            rbl = *(const uint4*)&Wl[src];
        }
#pragma unroll
        for (int ks = 0; ks < 2; ++ks) {
            int k0 = ks * 16 + tq * 2;
            int r0 = wm * 16 + gq;
            uint32_t ah0 = *(const uint32_t*)&Ahs[p][r0 * 40 + k0];
            uint32_t ah1 = *(const uint32_t*)&Ahs[p][(r0 + 8) * 40 + k0];
            uint32_t ah2 = *(const uint32_t*)&Ahs[p][r0 * 40 + k0 + 8];
            uint32_t ah3 = *(const uint32_t*)&Ahs[p][(r0 + 8) * 40 + k0 + 8];
            uint32_t al0 = *(const uint32_t*)&Als[p][r0 * 40 + k0];
            uint32_t al1 = *(const uint32_t*)&Als[p][(r0 + 8) * 40 + k0];
            uint32_t al2 = *(const uint32_t*)&Als[p][r0 * 40 + k0 + 8];
            uint32_t al3 = *(const uint32_t*)&Als[p][(r0 + 8) * 40 + k0 + 8];
#pragma unroll
            for (int nt = 0; nt < 4; ++nt) {
                int nr = wn * 32 + nt * 8 + gq;
                uint32_t bh0 = *(const uint32_t*)&Bhs[p][nr * 40 + k0];
                uint32_t bh1 = *(const uint32_t*)&Bhs[p][nr * 40 + k0 + 8];
                uint32_t bl0 = *(const uint32_t*)&Bls[p][nr * 40 + k0];
                uint32_t bl1 = *(const uint32_t*)&Bls[p][nr * 40 + k0 + 8];
                MMA_BF16(d[nt], ah0, ah1, ah2, ah3, bh0, bh1);
                MMA_BF16(d[nt], ah0, ah1, ah2, ah3, bl0, bl1);
                MMA_BF16(d[nt], al0, al1, al2, al3, bh0, bh1);
            }
        }
        if (i + 1 < niter) __syncthreads();
        p ^= 1;
    }

#pragma unroll
    for (int nt = 0; nt < 4; ++nt) {
        int ncol = n0 + wn * 32 + nt * 8 + tq * 2;
        int row0 = m0 + wm * 16 + gq;
        float b0 = 0.f, b1 = 0.f;
        if (Bv) { b0 = Bv[ncol]; b1 = Bv[ncol + 1]; }
#pragma unroll
        for (int h = 0; h < 2; ++h) {
            int row = row0 + h * 8;
            float v0 = d[nt][2 * h + 0] + b0;
            float v1 = d[nt][2 * h + 1] + b1;
            if (g.relu) { v0 = fmaxf(v0, 0.f); v1 = fmaxf(v1, 0.f); }
            size_t o = (size_t)row * g.ldc + ncol;
            if (Cf) { Cf[o] = v0; Cf[o + 1] = v1; }
            if (Ch) {
                __nv_bfloat16 hv[2], lv[2];
                hv[0] = __float2bfloat16(v0);
                lv[0] = __float2bfloat16(v0 - __bfloat162float(hv[0]));
                hv[1] = __float2bfloat16(v1);
                lv[1] = __float2bfloat16(v1 - __bfloat162float(hv[1]));
                *(uint32_t*)&Ch[o] = *(uint32_t*)hv;
                *(uint32_t*)&Cl[o] = *(uint32_t*)lv;
            }
        }
    }
}

// ---------------------------------------------------------------------------
// masked relational sum: fp32 in, bf16 hi/lo out
// ---------------------------------------------------------------------------
struct MaskArgs {
    const float* coor[4];
    int cbs[4];
    int cns[4];
    const float* relb;
};

__global__ void mask_relsum_kernel(MaskArgs ma) {
    int b = blockIdx.x, k = blockIdx.y;
    __shared__ float cx[NN], cy[NN], rr[NN], cnt[NN];
    __shared__ int   mask[NN][NN];
    int tid = threadIdx.x;
    if (tid < NN) {
        const float* cp = ma.coor[k] + (size_t)b * ma.cbs[k] + tid * ma.cns[k];
        cx[tid] = cp[0];
        cy[tid] = cp[1];
        rr[tid] = g_r[b * NN + tid];
    }
    __syncthreads();
    if (tid < NN * NN) {
        int i = tid / NN, j = tid % NN;
        float dx = cx[i] - cx[j], dy = cy[i] - cy[j];
        float dist = sqrtf(dx * dx + dy * dy);
        mask[i][j] = (i != j) && (dist <= rr[i] + rr[j]);
    }
    __syncthreads();
    if (tid < NN) {
        int c = 0;
        for (int j = 0; j < NN; ++j) c += mask[tid][j];
        cnt[tid] = (float)c;
    }
    __syncthreads();
    int d = tid;
    float rb = ma.relb[k * ND + d];
    size_t base = (size_t)k * SD + (size_t)b * NN * ND;
    float vv[NN];
#pragma unroll
    for (int j = 0; j < NN; ++j) vv[j] = g_v[base + j * ND + d];
#pragma unroll
    for (int i = 0; i < NN; ++i) {
        float acc = g_selfd[base + i * ND + d] + cnt[i] * (g_u[base + i * ND + d] + rb);
#pragma unroll
        for (int j = 0; j < NN; ++j)
            if (mask[i][j]) acc += vv[j];
        __nv_bfloat16 h = __float2bfloat16(acc);
        g_th[base + i * ND + d] = h;
        g_tl[base + i * ND + d] = __float2bfloat16(acc - __bfloat162float(h));
    }
}

// ---------------------------------------------------------------------------
// agg_finish
// ---------------------------------------------------------------------------
__global__ void agg_finish_kernel(const float* __restrict__ aggb,
                                  const float* __restrict__ dw,
                                  const float* __restrict__ db,
                                  float* __restrict__ out,
                                  __nv_bfloat16* __restrict__ Psth,
                                  __nv_bfloat16* __restrict__ Pstl, int it) {
    int row = blockIdx.x, tid = threadIdx.x;
    size_t off = (size_t)row * ND + tid;
    float s = aggb[tid] + g_aggp[off] + g_aggp[SD + off] +
              g_aggp[2 * SD + off] + g_aggp[3 * SD + off];
    __nv_bfloat16 h = __float2bfloat16(s);
    Psth[off] = h;
    Pstl[off] = __float2bfloat16(s - __bfloat162float(h));
    float p0 = s * dw[tid];
    float p1 = s * dw[256 + tid];
    float p2 = s * dw[512 + tid];
    float p3 = s * dw[768 + tid];
#pragma unroll
    for (int o = 16; o > 0; o >>= 1) {
        p0 += __shfl_down_sync(0xffffffffu, p0, o);
        p1 += __shfl_down_sync(0xffffffffu, p1, o);
        p2 += __shfl_down_sync(0xffffffffu, p2, o);
        p3 += __shfl_down_sync(0xffffffffu, p3, o);
    }
    __shared__ float sw[8][4];
    int wid = tid >> 5, lane = tid & 31;
    if (lane == 0) { sw[wid][0] = p0; sw[wid][1] = p1; sw[wid][2] = p2; sw[wid][3] = p3; }
    __syncthreads();
    if (tid < 4) {
        float acc = db[tid];
#pragma unroll
        for (int w = 0; w < 8; ++w) acc += sw[w][tid];
        int b = row / NN, n = row % NN;
        out[(size_t)b * (NROLL * NN * 4) + it * (NN * 4) + n * 4 + tid] = acc;
    }
}

// ---------------------------------------------------------------------------
// Host launchers
// ---------------------------------------------------------------------------
static void launch_gemm(int numZ, int M, int K1, int K2,
                        const float* const* A1, int lda1,
                        const float* const* A2, int lda2,
                        const float* const* W, const int* ldw,
                        const float* const* Bias,
                        float* const* C, int ldc, int relu) {
    GemmArgs ga;
    for (int z = 0; z < numZ; ++z) {
        ga.A1[z] = A1[z];
        ga.A2[z] = A2 ? A2[z] : A1[z];
        ga.W[z] = W[z];
        ga.Bias[z] = Bias ? Bias[z] : nullptr;
        ga.C[z] = C[z];
        ga.ldw[z] = ldw[z];
    }
    for (int z = numZ; z < 12; ++z) {
        ga.A1[z] = ga.A1[0]; ga.A2[z] = ga.A2[0]; ga.W[z] = ga.W[0];
        ga.Bias[z] = nullptr; ga.C[z] = ga.C[0]; ga.ldw[z] = ga.ldw[0];
    }
    ga.lda1 = lda1; ga.lda2 = lda2; ga.ldc = ldc;
    ga.K1 = K1; ga.K2 = K2; ga.relu = relu;
    dim3 grid(M / 64, 4, numZ);
    gemm_nt_kernel<<<grid, 256>>>(ga);
}

struct BfSpec {
    const __nv_bfloat16 *ah1, *al1, *ah2, *al2;
    int whoff;
    const float* bias;
    float* cf;
    __nv_bfloat16 *ch, *cl;
    int ldw;
};

static void launch_gemm_bf(int numZ, const BfSpec* sp,
                           int lda1, int lda2, int ldc, int K1, int K2, int relu) {
    GemmBfArgs ga;
    for (int z = 0; z < numZ; ++z) {
        ga.Ah1[z] = sp[z].ah1; ga.Al1[z] = sp[z].al1;
        ga.Ah2[z] = sp[z].ah2 ? sp[z].ah2 : sp[z].ah1;
        ga.Al2[z] = sp[z].al2 ? sp[z].al2 : sp[z].al1;
        ga.whoff[z] = sp[z].whoff;
        ga.Bias[z] = sp[z].bias;
        ga.Cf[z] = sp[z].cf;
        ga.Ch[z] = sp[z].ch;
        ga.Cl[z] = sp[z].cl;
        ga.ldw[z] = sp[z].ldw;
    }
    for (int z = numZ; z < 12; ++z) {
        ga.Ah1[z] = ga.Ah1[0]; ga.Al1[z] = ga.Al1[0];
        ga.Ah2[z] = ga.Ah2[0]; ga.Al2[z] = ga.Al2[0];
        ga.whoff[z] = ga.whoff[0]; ga.Bias[z] = nullptr;
        ga.Cf[z] = ga.Cf[0]; ga.Ch[z] = ga.Ch[0]; ga.Cl[z] = ga.Cl[0];
        ga.ldw[z] = ga.ldw[0];
    }
    ga.lda1 = lda1; ga.lda2 = lda2; ga.ldc = ldc;
    ga.K1 = K1; ga.K2 = K2; ga.relu = relu;
    dim3 grid(NROW / 64, 4, numZ);
    gemm_bf16_kernel<<<grid, 256>>>(ga);
}

extern "C" void kernel_launch(void* const* d_in, const int* in_sizes, int n_in,
                              void* d_out, int out_size) {
    const float* x       = (const float*)d_in[0];
    const float* rois    = (const float*)d_in[1];
    const float* src     = (const float*)d_in[2];
    const float* w_conv1 = (const float*)d_in[3];
    const float* b_conv1 = (const float*)d_in[4];
    const float* w_conv2 = (const float*)d_in[5];
    const float* b_conv2 = (const float*)d_in[6];
    const float* fc0_w   = (const float*)d_in[7];
    const float* fc0_b   = (const float*)d_in[8];
    const float* fc0c_w  = (const float*)d_in[9];
    const float* fc0c_b  = (const float*)d_in[10];
    const float* fc1c_w  = (const float*)d_in[11];
    const float* fc1c_b  = (const float*)d_in[12];
    const float* red_w   = (const float*)d_in[13];
    const float* red_b   = (const float*)d_in[14];
    const float* g_self_w = (const float*)d_in[15];
    const float* g_self_b = (const float*)d_in[16];
    const float* g_rel_w  = (const float*)d_in[17];
    const float* g_rel_b  = (const float*)d_in[18];
    const float* g_aff_w  = (const float*)d_in[19];
    const float* g_aff_b  = (const float*)d_in[20];
    const float* g_out_w  = (const float*)d_in[21];
    const float* g_out_b  = (const float*)d_in[22];
    const float* agg_w   = (const float*)d_in[23];
    const float* agg_b   = (const float*)d_in[24];
    const float* dec_w   = (const float*)d_in[25];
    const float* dec_b   = (const float*)d_in[26];
    float* outp = (float*)d_out;

    float *pool, *obj, *emb1, *emb2, *sttmp, *selfd, *u, *v, *aggp;
    __nv_bfloat16 *Oh, *Ol, *Ph, *Pl, *th, *tl, *ah, *al, *csh, *csl;
    cudaGetSymbolAddress((void**)&pool,  g_pool);
    cudaGetSymbolAddress((void**)&obj,   g_obj);
    cudaGetSymbolAddress((void**)&emb1,  g_emb1);
    cudaGetSymbolAddress((void**)&emb2,  g_emb2);
    cudaGetSymbolAddress((void**)&sttmp, g_sttmp);
    cudaGetSymbolAddress((void**)&selfd, g_selfd);
    cudaGetSymbolAddress((void**)&u,     g_u);
    cudaGetSymbolAddress((void**)&v,     g_v);
    cudaGetSymbolAddress((void**)&aggp,  g_aggp);
    cudaGetSymbolAddress((void**)&Oh,    g_Oh);
    cudaGetSymbolAddress((void**)&Ol,    g_Ol);
    cudaGetSymbolAddress((void**)&Ph,    g_Ph);
    cudaGetSymbolAddress((void**)&Pl,    g_Pl);
    cudaGetSymbolAddress((void**)&th,    g_th);
    cudaGetSymbolAddress((void**)&tl,    g_tl);
    cudaGetSymbolAddress((void**)&ah,    g_ah);
    cudaGetSymbolAddress((void**)&al,    g_al);
    cudaGetSymbolAddress((void**)&csh,   g_csh);
    cudaGetSymbolAddress((void**)&csl,   g_csl);

    // ---- conversions ----
    cvt2_kernel<<<144, 256>>>(w_conv2);
    cvt1_kernel<<<3, 256>>>(w_conv1);
    xcvt_kernel<<<16384, 256>>>(x);
    {
        CvtArgs ca;
        ca.src[0] = g_self_w; ca.size[0] = 262144; ca.off[0] = OFF_SELF;
        ca.src[1] = g_rel_w;  ca.size[1] = 524288; ca.off[1] = OFF_REL;
        ca.src[2] = g_aff_w;  ca.size[2] = 262144; ca.off[2] = OFF_AFF;
        ca.src[3] = g_out_w;  ca.size[3] = 524288; ca.off[3] = OFF_OUT;
        ca.src[4] = agg_w;    ca.size[4] = 262144; ca.off[4] = OFF_AGG;
        cvt_kernel<<<dim3(512, 5), 256>>>(ca);
    }

    // ---- preamble ----
    r_kernel<<<3, 128>>>(rois);
    conv1_mma_kernel<<<dim3(32, NBT), 256>>>(b_conv1);
    cudaFuncSetAttribute(conv2_mma_kernel,
                         cudaFuncAttributeMaxDynamicSharedMemorySize, CONV2_SMEM);
    conv2_mma_kernel<<<dim3(8, NBT), 256, CONV2_SMEM>>>(b_conv2);
    roi_kernel<<<NROI, 256>>>(rois);
    emb0_kernel<<<NROI, 256>>>(src, fc0c_w, fc0c_b);

    {   // fc1c
        const float* A1[1] = { emb1 };
        const float* W[1] = { fc1c_w }; int ldw[1] = { 256 };
        const float* B[1] = { fc1c_b };
        float* C[1] = { emb2 };
        launch_gemm(1, NROI, 256, 0, A1, 256, nullptr, 0, W, ldw, B, C, ND, 1);
    }
    {   // fc0
        const float* A1[1] = { pool };
        const float* W[1] = { fc0_w }; int ldw[1] = { 1024 };
        const float* B[1] = { fc0_b };
        float* C[1] = { obj };
        launch_gemm(1, NROI, 1024, 0, A1, 1024, nullptr, 0, W, ldw, B, C, ND, 1);
    }
    {   // red
        const float* A1[1] = { obj };
        const float* A2[1] = { emb2 };
        const float* W[1] = { red_w }; int ldw[1] = { 512 };
        const float* B[1] = { red_b };
        float* C[1] = { sttmp };
        launch_gemm(1, NROI, 256, 256, A1, 256, A2, 256, W, ldw, B, C, ND, 1);
    }
    rearr_kernel<<<NROI, 256>>>();

    // ---- rollouts ----
    for (int it = 0; it < NROLL; ++it) {
        const __nv_bfloat16 *sth[4], *stl[4];
        MaskArgs ma;
        for (int k = 0; k < 4; ++k) {
            int idx = it + k;
            if (idx < 4) {
                sth[k] = Oh + (size_t)idx * SD;
                stl[k] = Ol + (size_t)idx * SD;
                ma.coor[k] = src + idx * (NN * 2);
                ma.cbs[k] = NT * NN * 2;
                ma.cns[k] = 2;
            } else {
                sth[k] = Ph + (size_t)(idx - 4) * SD;
                stl[k] = Pl + (size_t)(idx - 4) * SD;
                ma.coor[k] = outp + (idx - 4) * (NN * 4) + 2;
                ma.cbs[k] = NROLL * NN * 4;
                ma.cns[k] = 4;
            }
        }
        ma.relb = g_rel_b;

        {   // selfd / u / v
            BfSpec sp[12];
            for (int z = 0; z < 12; ++z) {
                int k = z & 3, kind = z >> 2;
                sp[z].ah1 = sth[k]; sp[z].al1 = stl[k];
                sp[z].ah2 = nullptr; sp[z].al2 = nullptr;
                sp[z].ch = nullptr; sp[z].cl = nullptr;
                if (kind == 0)      { sp[z].whoff = OFF_SELF + k * 65536;       sp[z].ldw = 256; sp[z].bias = g_self_b + k * 256; sp[z].cf = selfd + (size_t)k * SD; }
                else if (kind == 1) { sp[z].whoff = OFF_REL + k * 131072;       sp[z].ldw = 512; sp[z].bias = nullptr;            sp[z].cf = u + (size_t)k * SD; }
                else                { sp[z].whoff = OFF_REL + k * 131072 + 256; sp[z].ldw = 512; sp[z].bias = nullptr;            sp[z].cf = v + (size_t)k * SD; }
            }
            launch_gemm_bf(12, sp, 256, 256, ND, 256, 0, 0);
        }
        mask_relsum_kernel<<<dim3(NB, 4), 256>>>(ma);
        {   // aff
            BfSpec sp[4];
            for (int k = 0; k < 4; ++k) {
                sp[k].ah1 = th + (size_t)k * SD; sp[k].al1 = tl + (size_t)k * SD;
                sp[k].ah2 = nullptr; sp[k].al2 = nullptr;
                sp[k].whoff = OFF_AFF + k * 65536; sp[k].ldw = 256;
                sp[k].bias = g_aff_b + k * 256;
                sp[k].cf = nullptr;
                sp[k].ch = ah + (size_t)k * SD; sp[k].cl = al + (size_t)k * SD;
            }
            launch_gemm_bf(4, sp, 256, 256, ND, 256, 0, 1);
        }
        {   // out
            BfSpec sp[4];
            for (int k = 0; k < 4; ++k) {
                sp[k].ah1 = ah + (size_t)k * SD; sp[k].al1 = al + (size_t)k * SD;
                sp[k].ah2 = sth[k]; sp[k].al2 = stl[k];
                sp[k].whoff = OFF_OUT + k * 131072; sp[k].ldw = 512;
                sp[k].bias = g_out_b + k * 256;
                sp[k].cf = nullptr;
                sp[k].ch = csh + k * 256; sp[k].cl = csl + k * 256;
            }
            launch_gemm_bf(4, sp, 256, 256, 1024, 256, 256, 1);
        }
        {   // agg split-K x4
            BfSpec sp[4];
            for (int z = 0; z < 4; ++z) {
                sp[z].ah1 = csh + z * 256; sp[z].al1 = csl + z * 256;
                sp[z].ah2 = nullptr; sp[z].al2 = nullptr;
                sp[z].whoff = OFF_AGG + z * 256; sp[z].ldw = 1024;
                sp[z].bias = nullptr;
                sp[z].cf = aggp + (size_t)z * SD;
                sp[z].ch = nullptr; sp[z].cl = nullptr;
            }
            launch_gemm_bf(4, sp, 1024, 1024, ND, 256, 0, 0);
        }
        agg_finish_kernel<<<NROW, 256>>>(agg_b, dec_w, dec_b, outp,
                                         Ph + (size_t)it * SD, Pl + (size_t)it * SD, it);
    }

    (void)in_sizes; (void)n_in; (void)out_size;
}